// round 1
// baseline (speedup 1.0000x reference)
#include <cuda_runtime.h>

#define NB 4
#define NS 2048
#define ND 1024
#define NH 16
#define DKH 64
#define MROWS (NB*NS)   // 8192

// Scratch (allocation-free rule: __device__ globals)
__device__ float g_q[NB*NH*NS*DKH];     // [B,H,S,dk]
__device__ float g_k[NB*NH*NS*DKH];
__device__ float g_v[NB*NH*NS*DKH];
__device__ float g_attn[MROWS*ND];      // [B,S,D] pre-Wo

// ---------------------------------------------------------------------------
// NT SGEMM: C[m,n] = sum_d A[m,d] * W[n,d].  M=8192, N=K=1024.
// 128x128 tile, BK=8, 8x8 microtile, 256 threads.
// HEADS=1: store into [B,H,S,dk] layout (for Q/K/V). HEADS=0: row-major [M,N].
// ---------------------------------------------------------------------------
template<int HEADS>
__global__ void __launch_bounds__(256, 2)
sgemm_nt(const float* __restrict__ A, const float* __restrict__ W,
         float* __restrict__ C)
{
    constexpr int K = ND;
    constexpr int N = ND;
    __shared__ float As[8][128];
    __shared__ float Bs[8][128];

    const int tid = threadIdx.x;
    const int lr  = tid >> 1;          // 0..127 row within tile
    const int lc  = (tid & 1) << 2;    // 0 or 4 (k-col group)
    const float* Ap = A + (size_t)(blockIdx.y * 128 + lr) * K + lc;
    const float* Wp = W + (size_t)(blockIdx.x * 128 + lr) * K + lc;

    const int ty = tid >> 4;           // 0..15
    const int tx = tid & 15;           // 0..15

    float acc[8][8];
    #pragma unroll
    for (int i = 0; i < 8; i++)
        #pragma unroll
        for (int j = 0; j < 8; j++) acc[i][j] = 0.f;

    for (int k0 = 0; k0 < K; k0 += 8) {
        float4 a4 = *(const float4*)(Ap + k0);
        float4 w4 = *(const float4*)(Wp + k0);
        As[lc+0][lr] = a4.x; As[lc+1][lr] = a4.y;
        As[lc+2][lr] = a4.z; As[lc+3][lr] = a4.w;
        Bs[lc+0][lr] = w4.x; Bs[lc+1][lr] = w4.y;
        Bs[lc+2][lr] = w4.z; Bs[lc+3][lr] = w4.w;
        __syncthreads();

        #pragma unroll
        for (int kk = 0; kk < 8; kk++) {
            float ra[8], rb[8];
            *(float4*)&ra[0] = *(const float4*)&As[kk][ty*8];
            *(float4*)&ra[4] = *(const float4*)&As[kk][ty*8+4];
            *(float4*)&rb[0] = *(const float4*)&Bs[kk][tx*8];
            *(float4*)&rb[4] = *(const float4*)&Bs[kk][tx*8+4];
            #pragma unroll
            for (int i = 0; i < 8; i++)
                #pragma unroll
                for (int j = 0; j < 8; j++)
                    acc[i][j] = fmaf(ra[i], rb[j], acc[i][j]);
        }
        __syncthreads();
    }

    const int row0 = blockIdx.y * 128 + ty * 8;
    const int col0 = blockIdx.x * 128 + tx * 8;

    #pragma unroll
    for (int i = 0; i < 8; i++) {
        float4 lo = make_float4(acc[i][0], acc[i][1], acc[i][2], acc[i][3]);
        float4 hi = make_float4(acc[i][4], acc[i][5], acc[i][6], acc[i][7]);
        if (HEADS) {
            const int m = row0 + i;
            const int b = m >> 11;            // S=2048
            const int s = m & (NS - 1);
            const int h = col0 >> 6;          // dk=64; 8-wide group never crosses head
            const int c = col0 & 63;
            float* dst = C + ((size_t)(b * NH + h) * NS + s) * DKH + c;
            *(float4*)dst       = lo;
            *(float4*)(dst + 4) = hi;
        } else {
            float* dst = C + (size_t)(row0 + i) * N + col0;
            *(float4*)dst       = lo;
            *(float4*)(dst + 4) = hi;
        }
    }
}

// ---------------------------------------------------------------------------
// Causal flash attention. One CTA = one (b*H+h, 64-row q-tile).
// 128 threads: ty=tid/8 owns 4 q-rows, tx=tid%8 owns 8 cols.
// Online softmax; O accumulator in registers; m/l in smem; shuffle row-reduce.
// ---------------------------------------------------------------------------
__global__ void __launch_bounds__(128)
attn_kernel(const float* __restrict__ Q, const float* __restrict__ K,
            const float* __restrict__ V, float* __restrict__ Oo)
{
    extern __shared__ float sm[];
    float* Qs  = sm;                 // 64 x 68
    float* Ks  = Qs + 64 * 68;
    float* Vs  = Ks + 64 * 68;
    float* Ps  = Vs + 64 * 68;
    float* m_s = Ps + 64 * 68;       // 64
    float* l_s = m_s + 64;           // 64

    const int bh  = blockIdx.x;      // b*H + h
    const int qt  = blockIdx.y;      // q tile
    const int tid = threadIdx.x;

    const float* Qb = Q + ((size_t)bh * NS + qt * 64) * DKH;
    const float* Kb = K + (size_t)bh * NS * DKH;
    const float* Vb = V + (size_t)bh * NS * DKH;

    // Load Q tile (64x64 floats, float4-vectorized, coalesced)
    #pragma unroll
    for (int i = 0; i < 8; i++) {
        int f = tid + i * 128;            // float4 index 0..1023
        int r = f >> 4, c = (f & 15) << 2;
        *(float4*)&Qs[r * 68 + c] = *(const float4*)&Qb[r * DKH + c];
    }
    if (tid < 64) { m_s[tid] = -1e30f; l_s[tid] = 0.f; }

    const int ty = tid >> 3;             // 0..15
    const int tx = tid & 7;              // 0..7
    const int qrow0 = qt * 64 + ty * 4;  // global q row of i=0

    float o[4][8];
    #pragma unroll
    for (int i = 0; i < 4; i++)
        #pragma unroll
        for (int j = 0; j < 8; j++) o[i][j] = 0.f;

    for (int kt = 0; kt <= qt; kt++) {
        __syncthreads();  // prior-iter reads of Ks/Vs/Ps complete
        const float* Kt = Kb + (size_t)kt * 64 * DKH;
        const float* Vt = Vb + (size_t)kt * 64 * DKH;
        #pragma unroll
        for (int i = 0; i < 8; i++) {
            int f = tid + i * 128;
            int r = f >> 4, c = (f & 15) << 2;
            *(float4*)&Ks[r * 68 + c] = *(const float4*)&Kt[r * DKH + c];
            *(float4*)&Vs[r * 68 + c] = *(const float4*)&Vt[r * DKH + c];
        }
        __syncthreads();

        // S = Q K^T
        float sv[4][8];
        #pragma unroll
        for (int i = 0; i < 4; i++)
            #pragma unroll
            for (int j = 0; j < 8; j++) sv[i][j] = 0.f;

        for (int kk = 0; kk < 64; kk += 4) {
            float4 qa[4], kb[8];
            #pragma unroll
            for (int i = 0; i < 4; i++)
                qa[i] = *(const float4*)&Qs[(ty * 4 + i) * 68 + kk];
            #pragma unroll
            for (int j = 0; j < 8; j++)
                kb[j] = *(const float4*)&Ks[(tx * 8 + j) * 68 + kk];
            #pragma unroll
            for (int i = 0; i < 4; i++)
                #pragma unroll
                for (int j = 0; j < 8; j++) {
                    sv[i][j] = fmaf(qa[i].x, kb[j].x, sv[i][j]);
                    sv[i][j] = fmaf(qa[i].y, kb[j].y, sv[i][j]);
                    sv[i][j] = fmaf(qa[i].z, kb[j].z, sv[i][j]);
                    sv[i][j] = fmaf(qa[i].w, kb[j].w, sv[i][j]);
                }
        }

        // Scale + causal mask + online softmax
        const int  kcol0 = kt * 64 + tx * 8;
        const bool diag  = (kt == qt);
        float rowscale[4], mnew[4], rsum[4];
        #pragma unroll
        for (int i = 0; i < 4; i++) {
            float mx = -1e30f;
            #pragma unroll
            for (int j = 0; j < 8; j++) {
                float val = sv[i][j] * 0.125f;  // 1/sqrt(64)
                if (diag && (kcol0 + j > qrow0 + i)) val = -1e30f;
                sv[i][j] = val;
                mx = fmaxf(mx, val);
            }
            mx = fmaxf(mx, __shfl_xor_sync(0xffffffffu, mx, 1));
            mx = fmaxf(mx, __shfl_xor_sync(0xffffffffu, mx, 2));
            mx = fmaxf(mx, __shfl_xor_sync(0xffffffffu, mx, 4));
            float mold = m_s[ty * 4 + i];
            float mn   = fmaxf(mold, mx);
            mnew[i]     = mn;
            rowscale[i] = __expf(mold - mn);
            float sum = 0.f;
            #pragma unroll
            for (int j = 0; j < 8; j++) {
                float p = __expf(sv[i][j] - mn);
                Ps[(ty * 4 + i) * 68 + tx * 8 + j] = p;
                sum += p;
            }
            sum += __shfl_xor_sync(0xffffffffu, sum, 1);
            sum += __shfl_xor_sync(0xffffffffu, sum, 2);
            sum += __shfl_xor_sync(0xffffffffu, sum, 4);
            rsum[i] = sum;
        }
        if (tx == 0) {
            #pragma unroll
            for (int i = 0; i < 4; i++) {
                m_s[ty * 4 + i] = mnew[i];
                l_s[ty * 4 + i] = l_s[ty * 4 + i] * rowscale[i] + rsum[i];
            }
        }
        #pragma unroll
        for (int i = 0; i < 4; i++)
            #pragma unroll
            for (int j = 0; j < 8; j++) o[i][j] *= rowscale[i];

        __syncthreads();  // Ps fully written

        // O += P @ V
        #pragma unroll 4
        for (int kk = 0; kk < 64; kk++) {
            float pa0 = Ps[(ty * 4 + 0) * 68 + kk];
            float pa1 = Ps[(ty * 4 + 1) * 68 + kk];
            float pa2 = Ps[(ty * 4 + 2) * 68 + kk];
            float pa3 = Ps[(ty * 4 + 3) * 68 + kk];
            float4 v0 = *(const float4*)&Vs[kk * 68 + tx * 8];
            float4 v1 = *(const float4*)&Vs[kk * 68 + tx * 8 + 4];
            o[0][0]=fmaf(pa0,v0.x,o[0][0]); o[0][1]=fmaf(pa0,v0.y,o[0][1]);
            o[0][2]=fmaf(pa0,v0.z,o[0][2]); o[0][3]=fmaf(pa0,v0.w,o[0][3]);
            o[0][4]=fmaf(pa0,v1.x,o[0][4]); o[0][5]=fmaf(pa0,v1.y,o[0][5]);
            o[0][6]=fmaf(pa0,v1.z,o[0][6]); o[0][7]=fmaf(pa0,v1.w,o[0][7]);
            o[1][0]=fmaf(pa1,v0.x,o[1][0]); o[1][1]=fmaf(pa1,v0.y,o[1][1]);
            o[1][2]=fmaf(pa1,v0.z,o[1][2]); o[1][3]=fmaf(pa1,v0.w,o[1][3]);
            o[1][4]=fmaf(pa1,v1.x,o[1][4]); o[1][5]=fmaf(pa1,v1.y,o[1][5]);
            o[1][6]=fmaf(pa1,v1.z,o[1][6]); o[1][7]=fmaf(pa1,v1.w,o[1][7]);
            o[2][0]=fmaf(pa2,v0.x,o[2][0]); o[2][1]=fmaf(pa2,v0.y,o[2][1]);
            o[2][2]=fmaf(pa2,v0.z,o[2][2]); o[2][3]=fmaf(pa2,v0.w,o[2][3]);
            o[2][4]=fmaf(pa2,v1.x,o[2][4]); o[2][5]=fmaf(pa2,v1.y,o[2][5]);
            o[2][6]=fmaf(pa2,v1.z,o[2][6]); o[2][7]=fmaf(pa2,v1.w,o[2][7]);
            o[3][0]=fmaf(pa3,v0.x,o[3][0]); o[3][1]=fmaf(pa3,v0.y,o[3][1]);
            o[3][2]=fmaf(pa3,v0.z,o[3][2]); o[3][3]=fmaf(pa3,v0.w,o[3][3]);
            o[3][4]=fmaf(pa3,v1.x,o[3][4]); o[3][5]=fmaf(pa3,v1.y,o[3][5]);
            o[3][6]=fmaf(pa3,v1.z,o[3][6]); o[3][7]=fmaf(pa3,v1.w,o[3][7]);
        }
    }

    __syncthreads();  // l_s final values visible

    // Epilogue: O / l, store to [B,S,D]
    const int b = bh >> 4;
    const int h = bh & 15;
    #pragma unroll
    for (int i = 0; i < 4; i++) {
        const int r  = ty * 4 + i;
        const float inv = 1.0f / l_s[r];
        const int gq = qt * 64 + r;
        float* dst = Oo + ((size_t)(b * NS + gq)) * ND + h * DKH + tx * 8;
        *(float4*)dst = make_float4(o[i][0]*inv, o[i][1]*inv, o[i][2]*inv, o[i][3]*inv);
        *(float4*)(dst + 4) = make_float4(o[i][4]*inv, o[i][5]*inv, o[i][6]*inv, o[i][7]*inv);
    }
}

// ---------------------------------------------------------------------------
extern "C" void kernel_launch(void* const* d_in, const int* in_sizes, int n_in,
                              void* d_out, int out_size)
{
    const float* x  = (const float*)d_in[0];
    const float* Wq = (const float*)d_in[1];
    const float* Wk = (const float*)d_in[2];
    const float* Wv = (const float*)d_in[3];
    const float* Wo = (const float*)d_in[4];
    float* out = (float*)d_out;

    float *q, *k, *v, *attn;
    cudaGetSymbolAddress((void**)&q,    g_q);
    cudaGetSymbolAddress((void**)&k,    g_k);
    cudaGetSymbolAddress((void**)&v,    g_v);
    cudaGetSymbolAddress((void**)&attn, g_attn);

    const int attn_smem = (4 * 64 * 68 + 2 * 64) * (int)sizeof(float);  // 70144 B
    cudaFuncSetAttribute(attn_kernel,
                         cudaFuncAttributeMaxDynamicSharedMemorySize, attn_smem);

    dim3 gGrid(ND / 128, MROWS / 128);  // (8, 64)
    sgemm_nt<1><<<gGrid, 256>>>(x, Wq, q);
    sgemm_nt<1><<<gGrid, 256>>>(x, Wk, k);
    sgemm_nt<1><<<gGrid, 256>>>(x, Wv, v);

    attn_kernel<<<dim3(NB * NH, NS / 64), 128, attn_smem>>>(q, k, v, attn);

    sgemm_nt<0><<<gGrid, 256>>>(attn, Wo, out);
}

// round 3
// speedup vs baseline: 1.2374x; 1.2374x over previous
#include <cuda_runtime.h>
#include <cuda_bf16.h>
#include <cstdint>

#define NB 4
#define NS 2048
#define ND 1024
#define NH 16
#define DKH 64
#define MROWS (NB*NS)   // 8192
#define KX 3072         // split-extended K (3 blocks of 1024)

// ---------------- scratch (__device__ globals; no allocation) ----------------
__device__ __nv_bfloat16 g_xs[(size_t)MROWS * KX];   // x split    [hi,lo,hi]
__device__ __nv_bfloat16 g_as[(size_t)MROWS * KX];   // attn split [hi,lo,hi]
__device__ __nv_bfloat16 g_wq[(size_t)ND * KX];      // weights    [hi,hi,lo]
__device__ __nv_bfloat16 g_wk[(size_t)ND * KX];
__device__ __nv_bfloat16 g_wv[(size_t)ND * KX];
__device__ __nv_bfloat16 g_wo[(size_t)ND * KX];
__device__ float g_q[(size_t)NB*NH*NS*DKH];          // [B,H,S,dk]
__device__ float g_k[(size_t)NB*NH*NS*DKH];
__device__ float g_v[(size_t)NB*NH*NS*DKH];
__device__ float g_attn[(size_t)MROWS * ND];         // [B,S,D] pre-Wo

// ---------------- helpers ----------------
__device__ __forceinline__ uint32_t smem_u32(const void* p) {
    uint32_t a;
    asm("{ .reg .u64 t; cvta.to.shared.u64 t, %1; cvt.u32.u64 %0, t; }" : "=r"(a) : "l"(p));
    return a;
}
__device__ __forceinline__ void ldsm4(uint32_t* r, uint32_t addr) {
    asm volatile("ldmatrix.sync.aligned.m8n8.x4.shared.b16 {%0,%1,%2,%3}, [%4];"
                 : "=r"(r[0]), "=r"(r[1]), "=r"(r[2]), "=r"(r[3]) : "r"(addr));
}
__device__ __forceinline__ void mma16816(float* c, const uint32_t* a, uint32_t b0, uint32_t b1) {
    asm volatile("mma.sync.aligned.m16n8k16.row.col.f32.bf16.bf16.f32 "
                 "{%0,%1,%2,%3}, {%4,%5,%6,%7}, {%8,%9}, {%0,%1,%2,%3};"
                 : "+f"(c[0]), "+f"(c[1]), "+f"(c[2]), "+f"(c[3])
                 : "r"(a[0]), "r"(a[1]), "r"(a[2]), "r"(a[3]), "r"(b0), "r"(b1));
}

// ---------------- fp32 -> split-bf16 conversion ----------------
// AMODE=1: blocks [hi, lo, hi] (activations)   AMODE=0: [hi, hi, lo] (weights)
template<int AMODE>
__global__ void split_bf16(const float* __restrict__ src, __nv_bfloat16* __restrict__ dst,
                           int rows)
{
    int i = blockIdx.x * blockDim.x + threadIdx.x;
    int total = rows * (ND / 2);
    if (i >= total) return;
    int r  = i >> 9;        // /512 pairs per row
    int cp = i & 511;
    float2 v = *(const float2*)(src + (size_t)r * ND + cp * 2);
    __nv_bfloat16 h0 = __float2bfloat16(v.x);
    __nv_bfloat16 h1 = __float2bfloat16(v.y);
    __nv_bfloat16 l0 = __float2bfloat16(v.x - __bfloat162float(h0));
    __nv_bfloat16 l1 = __float2bfloat16(v.y - __bfloat162float(h1));
    __nv_bfloat162 hh; hh.x = h0; hh.y = h1;
    __nv_bfloat162 ll; ll.x = l0; ll.y = l1;
    __nv_bfloat162* d2 = (__nv_bfloat162*)(dst + (size_t)r * KX) + cp;
    d2[0]    = hh;
    d2[512]  = AMODE ? ll : hh;
    d2[1024] = AMODE ? hh : ll;
}

// ---------------- HMMA bf16 NT GEMM: C[m,n] = sum_k A[m,k]*B[n,k] ----------------
// A: [MROWS,KX] bf16, B: [ND,KX] bf16, C fp32. CTA tile 128x128, BK=64, 256 thr,
// 8 warps in 2(M)x4(N); warp tile 64x32 = 4x4 m16n8k16. SW128-swizzled smem,
// double-buffered (64 KB), LDG->compute->STS overlap.
static constexpr int GEMM_NT   = KX / 64;   // 48 K-tiles
static constexpr int GEMM_SMEM = 2 * 2 * 16384;  // 65536

__device__ __forceinline__ void gemm_ldg(const __nv_bfloat16* __restrict__ A,
                                         const __nv_bfloat16* __restrict__ Bw,
                                         int m0, int n0, int k0,
                                         const int* lr, const int* lc,
                                         uint4* ra, uint4* rb)
{
    #pragma unroll
    for (int i = 0; i < 4; i++) {
        ra[i] = *(const uint4*)(A  + (size_t)(m0 + lr[i]) * KX + k0 + lc[i] * 8);
        rb[i] = *(const uint4*)(Bw + (size_t)(n0 + lr[i]) * KX + k0 + lc[i] * 8);
    }
}
__device__ __forceinline__ void gemm_sts(char* smem, int buf,
                                         const int* lr, const int* lc,
                                         const uint4* ra, const uint4* rb)
{
    char* ab = smem + buf * 32768;
    #pragma unroll
    for (int i = 0; i < 4; i++) {
        uint32_t off = (uint32_t)(lr[i] * 128 + lc[i] * 16);
        off ^= (off >> 3) & 0x70;
        *(uint4*)(ab + off)         = ra[i];
        *(uint4*)(ab + 16384 + off) = rb[i];
    }
}

template<int HEADS>
__global__ void __launch_bounds__(256)
gemm_mma(const __nv_bfloat16* __restrict__ A, const __nv_bfloat16* __restrict__ Bw,
         float* __restrict__ C)
{
    extern __shared__ __align__(1024) char smem[];
    const int tid  = threadIdx.x;
    const int lane = tid & 31;
    const int wid  = tid >> 5;
    const int warp_m = wid & 1;    // 0..1 (64 rows each)
    const int warp_n = wid >> 1;   // 0..3 (32 cols each)
    const int m0 = blockIdx.y * 128;
    const int n0 = blockIdx.x * 128;

    const uint32_t sbase = smem_u32(smem);

    int lr[4], lc[4];
    #pragma unroll
    for (int i = 0; i < 4; i++) { int ci = tid + i * 256; lr[i] = ci >> 3; lc[i] = ci & 7; }

    const int qrow = lane & 15;    // ldmatrix source row within 16-row block
    const int qcol = lane >> 4;    // 0/1: which 16B half of the k16 slice

    float acc[4][4][4];
    #pragma unroll
    for (int a = 0; a < 4; a++)
        #pragma unroll
        for (int b = 0; b < 4; b++)
            #pragma unroll
            for (int c = 0; c < 4; c++) acc[a][b][c] = 0.f;

    uint4 ra[4], rb[4];
    gemm_ldg(A, Bw, m0, n0, 0, lr, lc, ra, rb);
    gemm_sts(smem, 0, lr, lc, ra, rb);
    __syncthreads();

    #pragma unroll 1
    for (int t = 0; t < GEMM_NT; t++) {
        if (t + 1 < GEMM_NT)
            gemm_ldg(A, Bw, m0, n0, (t + 1) * 64, lr, lc, ra, rb);

        const uint32_t sA = sbase + (uint32_t)(t & 1) * 32768u;
        const uint32_t sB = sA + 16384u;

        #pragma unroll
        for (int ks = 0; ks < 4; ks++) {
            uint32_t afr[4][4], bfr[2][4];
            #pragma unroll
            for (int mi = 0; mi < 4; mi++) {
                uint32_t off = (uint32_t)((warp_m * 64 + mi * 16 + qrow) * 128
                                          + (ks * 2 + qcol) * 16);
                ldsm4(afr[mi], sA + (off ^ ((off >> 3) & 0x70)));
            }
            #pragma unroll
            for (int nj = 0; nj < 2; nj++) {
                uint32_t off = (uint32_t)((warp_n * 32 + nj * 16 + qrow) * 128
                                          + (ks * 2 + qcol) * 16);
                ldsm4(bfr[nj], sB + (off ^ ((off >> 3) & 0x70)));
            }
            #pragma unroll
            for (int mi = 0; mi < 4; mi++)
                #pragma unroll
                for (int ni = 0; ni < 4; ni++)
                    mma16816(acc[mi][ni], afr[mi],
                             bfr[ni >> 1][ni & 1], bfr[ni >> 1][2 + (ni & 1)]);
        }

        if (t + 1 < GEMM_NT)
            gemm_sts(smem, (t + 1) & 1, lr, lc, ra, rb);
        __syncthreads();
    }

    // epilogue: c0,c1 -> (row, col..col+1); c2,c3 -> (row+8, ..)
    const int tr = lane >> 2;
    const int tc = (lane & 3) * 2;
    #pragma unroll
    for (int mi = 0; mi < 4; mi++) {
        #pragma unroll
        for (int ni = 0; ni < 4; ni++) {
            const int row = m0 + warp_m * 64 + mi * 16 + tr;
            const int col = n0 + warp_n * 32 + ni * 8 + tc;
            float* cc = acc[mi][ni];
            #pragma unroll
            for (int half = 0; half < 2; half++) {
                const int r = row + half * 8;
                float2 val = half ? make_float2(cc[2], cc[3]) : make_float2(cc[0], cc[1]);
                if (HEADS) {
                    const int b = r >> 11, s = r & (NS - 1);
                    const int h = col >> 6, ch = col & 63;
                    *(float2*)(C + ((size_t)(b * NH + h) * NS + s) * DKH + ch) = val;
                } else {
                    *(float2*)(C + (size_t)r * ND + col) = val;
                }
            }
        }
    }
}

// ---------------------------------------------------------------------------
// Causal flash attention (unchanged). One CTA = (b*H+h, 64-row q-tile).
// ---------------------------------------------------------------------------
__global__ void __launch_bounds__(128)
attn_kernel(const float* __restrict__ Q, const float* __restrict__ K,
            const float* __restrict__ V, float* __restrict__ Oo)
{
    extern __shared__ float sm[];
    float* Qs  = sm;
    float* Ks  = Qs + 64 * 68;
    float* Vs  = Ks + 64 * 68;
    float* Ps  = Vs + 64 * 68;
    float* m_s = Ps + 64 * 68;
    float* l_s = m_s + 64;

    const int bh  = blockIdx.x;
    const int qt  = blockIdx.y;
    const int tid = threadIdx.x;

    const float* Qb = Q + ((size_t)bh * NS + qt * 64) * DKH;
    const float* Kb = K + (size_t)bh * NS * DKH;
    const float* Vb = V + (size_t)bh * NS * DKH;

    #pragma unroll
    for (int i = 0; i < 8; i++) {
        int f = tid + i * 128;
        int r = f >> 4, c = (f & 15) << 2;
        *(float4*)&Qs[r * 68 + c] = *(const float4*)&Qb[r * DKH + c];
    }
    if (tid < 64) { m_s[tid] = -1e30f; l_s[tid] = 0.f; }

    const int ty = tid >> 3;
    const int tx = tid & 7;
    const int qrow0 = qt * 64 + ty * 4;

    float o[4][8];
    #pragma unroll
    for (int i = 0; i < 4; i++)
        #pragma unroll
        for (int j = 0; j < 8; j++) o[i][j] = 0.f;

    for (int kt = 0; kt <= qt; kt++) {
        __syncthreads();
        const float* Kt = Kb + (size_t)kt * 64 * DKH;
        const float* Vt = Vb + (size_t)kt * 64 * DKH;
        #pragma unroll
        for (int i = 0; i < 8; i++) {
            int f = tid + i * 128;
            int r = f >> 4, c = (f & 15) << 2;
            *(float4*)&Ks[r * 68 + c] = *(const float4*)&Kt[r * DKH + c];
            *(float4*)&Vs[r * 68 + c] = *(const float4*)&Vt[r * DKH + c];
        }
        __syncthreads();

        float sv[4][8];
        #pragma unroll
        for (int i = 0; i < 4; i++)
            #pragma unroll
            for (int j = 0; j < 8; j++) sv[i][j] = 0.f;

        for (int kk = 0; kk < 64; kk += 4) {
            float4 qa[4], kb[8];
            #pragma unroll
            for (int i = 0; i < 4; i++)
                qa[i] = *(const float4*)&Qs[(ty * 4 + i) * 68 + kk];
            #pragma unroll
            for (int j = 0; j < 8; j++)
                kb[j] = *(const float4*)&Ks[(tx * 8 + j) * 68 + kk];
            #pragma unroll
            for (int i = 0; i < 4; i++)
                #pragma unroll
                for (int j = 0; j < 8; j++) {
                    sv[i][j] = fmaf(qa[i].x, kb[j].x, sv[i][j]);
                    sv[i][j] = fmaf(qa[i].y, kb[j].y, sv[i][j]);
                    sv[i][j] = fmaf(qa[i].z, kb[j].z, sv[i][j]);
                    sv[i][j] = fmaf(qa[i].w, kb[j].w, sv[i][j]);
                }
        }

        const int  kcol0 = kt * 64 + tx * 8;
        const bool diag  = (kt == qt);
        float rowscale[4], mnew[4], rsum[4];
        #pragma unroll
        for (int i = 0; i < 4; i++) {
            float mx = -1e30f;
            #pragma unroll
            for (int j = 0; j < 8; j++) {
                float val = sv[i][j] * 0.125f;
                if (diag && (kcol0 + j > qrow0 + i)) val = -1e30f;
                sv[i][j] = val;
                mx = fmaxf(mx, val);
            }
            mx = fmaxf(mx, __shfl_xor_sync(0xffffffffu, mx, 1));
            mx = fmaxf(mx, __shfl_xor_sync(0xffffffffu, mx, 2));
            mx = fmaxf(mx, __shfl_xor_sync(0xffffffffu, mx, 4));
            float mold = m_s[ty * 4 + i];
            float mn   = fmaxf(mold, mx);
            mnew[i]     = mn;
            rowscale[i] = __expf(mold - mn);
            float sum = 0.f;
            #pragma unroll
            for (int j = 0; j < 8; j++) {
                float p = __expf(sv[i][j] - mn);
                Ps[(ty * 4 + i) * 68 + tx * 8 + j] = p;
                sum += p;
            }
            sum += __shfl_xor_sync(0xffffffffu, sum, 1);
            sum += __shfl_xor_sync(0xffffffffu, sum, 2);
            sum += __shfl_xor_sync(0xffffffffu, sum, 4);
            rsum[i] = sum;
        }
        if (tx == 0) {
            #pragma unroll
            for (int i = 0; i < 4; i++) {
                m_s[ty * 4 + i] = mnew[i];
                l_s[ty * 4 + i] = l_s[ty * 4 + i] * rowscale[i] + rsum[i];
            }
        }
        #pragma unroll
        for (int i = 0; i < 4; i++)
            #pragma unroll
            for (int j = 0; j < 8; j++) o[i][j] *= rowscale[i];

        __syncthreads();

        #pragma unroll 4
        for (int kk = 0; kk < 64; kk++) {
            float pa0 = Ps[(ty * 4 + 0) * 68 + kk];
            float pa1 = Ps[(ty * 4 + 1) * 68 + kk];
            float pa2 = Ps[(ty * 4 + 2) * 68 + kk];
            float pa3 = Ps[(ty * 4 + 3) * 68 + kk];
            float4 v0 = *(const float4*)&Vs[kk * 68 + tx * 8];
            float4 v1 = *(const float4*)&Vs[kk * 68 + tx * 8 + 4];
            o[0][0]=fmaf(pa0,v0.x,o[0][0]); o[0][1]=fmaf(pa0,v0.y,o[0][1]);
            o[0][2]=fmaf(pa0,v0.z,o[0][2]); o[0][3]=fmaf(pa0,v0.w,o[0][3]);
            o[0][4]=fmaf(pa0,v1.x,o[0][4]); o[0][5]=fmaf(pa0,v1.y,o[0][5]);
            o[0][6]=fmaf(pa0,v1.z,o[0][6]); o[0][7]=fmaf(pa0,v1.w,o[0][7]);
            o[1][0]=fmaf(pa1,v0.x,o[1][0]); o[1][1]=fmaf(pa1,v0.y,o[1][1]);
            o[1][2]=fmaf(pa1,v0.z,o[1][2]); o[1][3]=fmaf(pa1,v0.w,o[1][3]);
            o[1][4]=fmaf(pa1,v1.x,o[1][4]); o[1][5]=fmaf(pa1,v1.y,o[1][5]);
            o[1][6]=fmaf(pa1,v1.z,o[1][6]); o[1][7]=fmaf(pa1,v1.w,o[1][7]);
            o[2][0]=fmaf(pa2,v0.x,o[2][0]); o[2][1]=fmaf(pa2,v0.y,o[2][1]);
            o[2][2]=fmaf(pa2,v0.z,o[2][2]); o[2][3]=fmaf(pa2,v0.w,o[2][3]);
            o[2][4]=fmaf(pa2,v1.x,o[2][4]); o[2][5]=fmaf(pa2,v1.y,o[2][5]);
            o[2][6]=fmaf(pa2,v1.z,o[2][6]); o[2][7]=fmaf(pa2,v1.w,o[2][7]);
            o[3][0]=fmaf(pa3,v0.x,o[3][0]); o[3][1]=fmaf(pa3,v0.y,o[3][1]);
            o[3][2]=fmaf(pa3,v0.z,o[3][2]); o[3][3]=fmaf(pa3,v0.w,o[3][3]);
            o[3][4]=fmaf(pa3,v1.x,o[3][4]); o[3][5]=fmaf(pa3,v1.y,o[3][5]);
            o[3][6]=fmaf(pa3,v1.z,o[3][6]); o[3][7]=fmaf(pa3,v1.w,o[3][7]);
        }
    }

    __syncthreads();

    const int b = bh >> 4;
    const int h = bh & 15;
    #pragma unroll
    for (int i = 0; i < 4; i++) {
        const int r  = ty * 4 + i;
        const float inv = 1.0f / l_s[r];
        const int gq = qt * 64 + r;
        float* dst = Oo + ((size_t)(b * NS + gq)) * ND + h * DKH + tx * 8;
        *(float4*)dst = make_float4(o[i][0]*inv, o[i][1]*inv, o[i][2]*inv, o[i][3]*inv);
        *(float4*)(dst + 4) = make_float4(o[i][4]*inv, o[i][5]*inv, o[i][6]*inv, o[i][7]*inv);
    }
}

// ---------------------------------------------------------------------------
extern "C" void kernel_launch(void* const* d_in, const int* in_sizes, int n_in,
                              void* d_out, int out_size)
{
    const float* x  = (const float*)d_in[0];
    const float* Wq = (const float*)d_in[1];
    const float* Wk = (const float*)d_in[2];
    const float* Wv = (const float*)d_in[3];
    const float* Wo = (const float*)d_in[4];
    float* out = (float*)d_out;

    __nv_bfloat16 *xs, *as, *wq, *wk, *wv, *wo;
    float *q, *k, *v, *attn;
    cudaGetSymbolAddress((void**)&xs, g_xs);
    cudaGetSymbolAddress((void**)&as, g_as);
    cudaGetSymbolAddress((void**)&wq, g_wq);
    cudaGetSymbolAddress((void**)&wk, g_wk);
    cudaGetSymbolAddress((void**)&wv, g_wv);
    cudaGetSymbolAddress((void**)&wo, g_wo);
    cudaGetSymbolAddress((void**)&q,  g_q);
    cudaGetSymbolAddress((void**)&k,  g_k);
    cudaGetSymbolAddress((void**)&v,  g_v);
    cudaGetSymbolAddress((void**)&attn, g_attn);

    cudaFuncSetAttribute(gemm_mma<0>, cudaFuncAttributeMaxDynamicSharedMemorySize, GEMM_SMEM);
    cudaFuncSetAttribute(gemm_mma<1>, cudaFuncAttributeMaxDynamicSharedMemorySize, GEMM_SMEM);
    const int attn_smem = (4 * 64 * 68 + 2 * 64) * (int)sizeof(float);
    cudaFuncSetAttribute(attn_kernel, cudaFuncAttributeMaxDynamicSharedMemorySize, attn_smem);

    // conversions
    {
        int tx = MROWS * (ND / 2);
        split_bf16<1><<<(tx + 255) / 256, 256>>>(x, xs, MROWS);
        int tw = ND * (ND / 2);
        split_bf16<0><<<(tw + 255) / 256, 256>>>(Wq, wq, ND);
        split_bf16<0><<<(tw + 255) / 256, 256>>>(Wk, wk, ND);
        split_bf16<0><<<(tw + 255) / 256, 256>>>(Wv, wv, ND);
        split_bf16<0><<<(tw + 255) / 256, 256>>>(Wo, wo, ND);
    }

    dim3 gGrid(ND / 128, MROWS / 128);  // (8, 64)
    gemm_mma<1><<<gGrid, 256, GEMM_SMEM>>>(xs, wq, q);
    gemm_mma<1><<<gGrid, 256, GEMM_SMEM>>>(xs, wk, k);
    gemm_mma<1><<<gGrid, 256, GEMM_SMEM>>>(xs, wv, v);

    attn_kernel<<<dim3(NB * NH, NS / 64), 128, attn_smem>>>(q, k, v, attn);

    {
        int tx = MROWS * (ND / 2);
        split_bf16<1><<<(tx + 255) / 256, 256>>>(attn, as, MROWS);
    }
    gemm_mma<0><<<gGrid, 256, GEMM_SMEM>>>(as, wo, out);
}

// round 4
// speedup vs baseline: 3.5462x; 2.8659x over previous
#include <cuda_runtime.h>
#include <cuda_bf16.h>
#include <cstdint>

#define NB 4
#define NS 2048
#define ND 1024
#define NH 16
#define DKH 64
#define MROWS (NB*NS)   // 8192
#define KX 3072         // split-extended K (3 blocks of 1024)

// ---------------- scratch (__device__ globals; no allocation) ----------------
__device__ __nv_bfloat16 g_xs[(size_t)MROWS * KX];   // x split    [hi,lo,hi]
__device__ __nv_bfloat16 g_as[(size_t)MROWS * KX];   // attn split [hi,lo,hi]
__device__ __nv_bfloat16 g_wq[(size_t)ND * KX];      // weights    [hi,hi,lo]
__device__ __nv_bfloat16 g_wk[(size_t)ND * KX];
__device__ __nv_bfloat16 g_wv[(size_t)ND * KX];
__device__ __nv_bfloat16 g_wo[(size_t)ND * KX];
// split-bf16 Q/K/V: [bh][plane(hi=0,lo=1)][S][64]
__device__ __nv_bfloat16 g_q[(size_t)NB*NH*2*NS*DKH];
__device__ __nv_bfloat16 g_k[(size_t)NB*NH*2*NS*DKH];
__device__ __nv_bfloat16 g_v[(size_t)NB*NH*2*NS*DKH];
__device__ float g_attn[(size_t)MROWS * ND];         // [B,S,D] pre-Wo

// ---------------- helpers ----------------
__device__ __forceinline__ uint32_t smem_u32(const void* p) {
    uint32_t a;
    asm("{ .reg .u64 t; cvta.to.shared.u64 t, %1; cvt.u32.u64 %0, t; }" : "=r"(a) : "l"(p));
    return a;
}
__device__ __forceinline__ void ldsm4(uint32_t* r, uint32_t addr) {
    asm volatile("ldmatrix.sync.aligned.m8n8.x4.shared.b16 {%0,%1,%2,%3}, [%4];"
                 : "=r"(r[0]), "=r"(r[1]), "=r"(r[2]), "=r"(r[3]) : "r"(addr));
}
__device__ __forceinline__ void ldsm4t(uint32_t* r, uint32_t addr) {
    asm volatile("ldmatrix.sync.aligned.m8n8.x4.trans.shared.b16 {%0,%1,%2,%3}, [%4];"
                 : "=r"(r[0]), "=r"(r[1]), "=r"(r[2]), "=r"(r[3]) : "r"(addr));
}
__device__ __forceinline__ void mma16816(float* c, const uint32_t* a, uint32_t b0, uint32_t b1) {
    asm volatile("mma.sync.aligned.m16n8k16.row.col.f32.bf16.bf16.f32 "
                 "{%0,%1,%2,%3}, {%4,%5,%6,%7}, {%8,%9}, {%0,%1,%2,%3};"
                 : "+f"(c[0]), "+f"(c[1]), "+f"(c[2]), "+f"(c[3])
                 : "r"(a[0]), "r"(a[1]), "r"(a[2]), "r"(a[3]), "r"(b0), "r"(b1));
}
__device__ __forceinline__ void cpasync16(uint32_t dst, const void* src) {
    asm volatile("cp.async.cg.shared.global [%0], [%1], 16;" :: "r"(dst), "l"(src));
}
__device__ __forceinline__ uint32_t packbf(float a, float b) {
    __nv_bfloat162 h = __floats2bfloat162_rn(a, b);
    return *(uint32_t*)&h;
}
__device__ __forceinline__ uint32_t packlo(float a, float b, uint32_t hbits) {
    __nv_bfloat162 h = *(__nv_bfloat162*)&hbits;
    return packbf(a - __bfloat162float(h.x), b - __bfloat162float(h.y));
}

// ---------------- fp32 -> split-bf16 conversion ----------------
// AMODE=1: blocks [hi, lo, hi] (activations)   AMODE=0: [hi, hi, lo] (weights)
template<int AMODE>
__global__ void split_bf16(const float* __restrict__ src, __nv_bfloat16* __restrict__ dst,
                           int rows)
{
    int i = blockIdx.x * blockDim.x + threadIdx.x;
    int total = rows * (ND / 2);
    if (i >= total) return;
    int r  = i >> 9;
    int cp = i & 511;
    float2 v = *(const float2*)(src + (size_t)r * ND + cp * 2);
    __nv_bfloat16 h0 = __float2bfloat16(v.x);
    __nv_bfloat16 h1 = __float2bfloat16(v.y);
    __nv_bfloat16 l0 = __float2bfloat16(v.x - __bfloat162float(h0));
    __nv_bfloat16 l1 = __float2bfloat16(v.y - __bfloat162float(h1));
    __nv_bfloat162 hh; hh.x = h0; hh.y = h1;
    __nv_bfloat162 ll; ll.x = l0; ll.y = l1;
    __nv_bfloat162* d2 = (__nv_bfloat162*)(dst + (size_t)r * KX) + cp;
    d2[0]    = hh;
    d2[512]  = AMODE ? ll : hh;
    d2[1024] = AMODE ? hh : ll;
}

// ---------------- HMMA bf16 NT GEMM: C[m,n] = sum_k A[m,k]*B[n,k] ----------------
// OMODE 0: fp32 [M,ND]; OMODE 1: split bf16 head layout; OMODE 2: like 1 but *0.125
static constexpr int GEMM_NT   = KX / 64;        // 48 K-tiles
static constexpr int GEMM_SMEM = 2 * 2 * 16384;  // 65536

__device__ __forceinline__ void gemm_ldg(const __nv_bfloat16* __restrict__ A,
                                         const __nv_bfloat16* __restrict__ Bw,
                                         int m0, int n0, int k0,
                                         const int* lr, const int* lc,
                                         uint4* ra, uint4* rb)
{
    #pragma unroll
    for (int i = 0; i < 4; i++) {
        ra[i] = *(const uint4*)(A  + (size_t)(m0 + lr[i]) * KX + k0 + lc[i] * 8);
        rb[i] = *(const uint4*)(Bw + (size_t)(n0 + lr[i]) * KX + k0 + lc[i] * 8);
    }
}
__device__ __forceinline__ void gemm_sts(char* smem, int buf,
                                         const int* lr, const int* lc,
                                         const uint4* ra, const uint4* rb)
{
    char* ab = smem + buf * 32768;
    #pragma unroll
    for (int i = 0; i < 4; i++) {
        uint32_t off = (uint32_t)(lr[i] * 128 + lc[i] * 16);
        off ^= (off >> 3) & 0x70;
        *(uint4*)(ab + off)         = ra[i];
        *(uint4*)(ab + 16384 + off) = rb[i];
    }
}

template<int OMODE>
__global__ void __launch_bounds__(256)
gemm_mma(const __nv_bfloat16* __restrict__ A, const __nv_bfloat16* __restrict__ Bw,
         void* __restrict__ Cv)
{
    extern __shared__ __align__(1024) char smem[];
    const int tid  = threadIdx.x;
    const int lane = tid & 31;
    const int wid  = tid >> 5;
    const int warp_m = wid & 1;
    const int warp_n = wid >> 1;
    const int m0 = blockIdx.y * 128;
    const int n0 = blockIdx.x * 128;

    const uint32_t sbase = smem_u32(smem);

    int lr[4], lc[4];
    #pragma unroll
    for (int i = 0; i < 4; i++) { int ci = tid + i * 256; lr[i] = ci >> 3; lc[i] = ci & 7; }

    const int qrow = lane & 15;
    const int qcol = lane >> 4;

    float acc[4][4][4];
    #pragma unroll
    for (int a = 0; a < 4; a++)
        #pragma unroll
        for (int b = 0; b < 4; b++)
            #pragma unroll
            for (int c = 0; c < 4; c++) acc[a][b][c] = 0.f;

    uint4 ra[4], rb[4];
    gemm_ldg(A, Bw, m0, n0, 0, lr, lc, ra, rb);
    gemm_sts(smem, 0, lr, lc, ra, rb);
    __syncthreads();

    #pragma unroll 1
    for (int t = 0; t < GEMM_NT; t++) {
        if (t + 1 < GEMM_NT)
            gemm_ldg(A, Bw, m0, n0, (t + 1) * 64, lr, lc, ra, rb);

        const uint32_t sA = sbase + (uint32_t)(t & 1) * 32768u;
        const uint32_t sB = sA + 16384u;

        #pragma unroll
        for (int ks = 0; ks < 4; ks++) {
            uint32_t afr[4][4], bfr[2][4];
            #pragma unroll
            for (int mi = 0; mi < 4; mi++) {
                uint32_t off = (uint32_t)((warp_m * 64 + mi * 16 + qrow) * 128
                                          + (ks * 2 + qcol) * 16);
                ldsm4(afr[mi], sA + (off ^ ((off >> 3) & 0x70)));
            }
            #pragma unroll
            for (int nj = 0; nj < 2; nj++) {
                uint32_t off = (uint32_t)((warp_n * 32 + nj * 16 + qrow) * 128
                                          + (ks * 2 + qcol) * 16);
                ldsm4(bfr[nj], sB + (off ^ ((off >> 3) & 0x70)));
            }
            #pragma unroll
            for (int mi = 0; mi < 4; mi++)
                #pragma unroll
                for (int ni = 0; ni < 4; ni++)
                    mma16816(acc[mi][ni], afr[mi],
                             bfr[ni >> 1][ni & 1], bfr[ni >> 1][2 + (ni & 1)]);
        }

        if (t + 1 < GEMM_NT)
            gemm_sts(smem, (t + 1) & 1, lr, lc, ra, rb);
        __syncthreads();
    }

    const int tr = lane >> 2;
    const int tc = (lane & 3) * 2;
    #pragma unroll
    for (int mi = 0; mi < 4; mi++) {
        #pragma unroll
        for (int ni = 0; ni < 4; ni++) {
            const int row = m0 + warp_m * 64 + mi * 16 + tr;
            const int col = n0 + warp_n * 32 + ni * 8 + tc;
            float* cc = acc[mi][ni];
            #pragma unroll
            for (int half = 0; half < 2; half++) {
                const int r = row + half * 8;
                float2 val = half ? make_float2(cc[2], cc[3]) : make_float2(cc[0], cc[1]);
                if (OMODE == 0) {
                    *(float2*)((float*)Cv + (size_t)r * ND + col) = val;
                } else {
                    if (OMODE == 2) { val.x *= 0.125f; val.y *= 0.125f; }
                    const int b = r >> 11, s = r & (NS - 1);
                    const int h = col >> 6, ch = col & 63;
                    __nv_bfloat162 hi = __floats2bfloat162_rn(val.x, val.y);
                    __nv_bfloat162 lo = __floats2bfloat162_rn(
                        val.x - __bfloat162float(hi.x), val.y - __bfloat162float(hi.y));
                    __nv_bfloat16* base = (__nv_bfloat16*)Cv
                        + (((size_t)(b * NH + h) * 2) * NS + s) * 64 + ch;
                    *(__nv_bfloat162*)base            = hi;
                    *(__nv_bfloat162*)(base + NS*64)  = lo;
                }
            }
        }
    }
}

// ---------------------------------------------------------------------------
// HMMA causal flash attention. CTA = (bh, 128 q-rows). 4 warps x 32 rows.
// QK^T 3 passes (qh*kh + ql*kh + qh*kl); softmax fp32; PV 3 passes
// (ph*vh + pl*vh + ph*vl). kv tiles of 64 double-buffered via cp.async.
// smem: Q 2x16KB | 2 bufs x (Kh,Kl,Vh,Vl) 4x8KB  = 96KB.
// ---------------------------------------------------------------------------
static constexpr int ATTN_SMEM = 32768 + 2 * 32768;  // 98304

__global__ void __launch_bounds__(128)
fattn(const __nv_bfloat16* __restrict__ Qg, const __nv_bfloat16* __restrict__ Kg,
      const __nv_bfloat16* __restrict__ Vg, float* __restrict__ Og)
{
    extern __shared__ __align__(1024) char sm[];
    const uint32_t sb = smem_u32(sm);
    const int bh  = blockIdx.x;
    const int qt  = (int)gridDim.y - 1 - (int)blockIdx.y;  // big tiles first
    const int tid = threadIdx.x, lane = tid & 31, w = tid >> 5;

    const __nv_bfloat16* Qbh = Qg + (size_t)bh * 2 * NS * 64;
    const __nv_bfloat16* Kbh = Kg + (size_t)bh * 2 * NS * 64;
    const __nv_bfloat16* Vbh = Vg + (size_t)bh * 2 * NS * 64;

    // Q tile: 2 planes x 128 x 64, swizzled
    #pragma unroll
    for (int i = 0; i < 16; i++) {
        int c = tid + i * 128;             // 0..2047 16B chunks
        int p = c >> 10, r = (c >> 3) & 127, col16 = c & 7;
        uint4 v = *(const uint4*)(Qbh + (size_t)p * NS * 64
                                  + (size_t)(qt * 128 + r) * 64 + col16 * 8);
        uint32_t off = (uint32_t)(r * 128 + col16 * 16);
        *(uint4*)(sm + p * 16384 + (off ^ ((off >> 3) & 0x70))) = v;
    }

    const int nkt = 2 * qt + 2;

    // async loader for kv tile kt -> buf
    auto load_kv = [&](int kt, int buf) {
        const int kv0 = kt * 64;
        #pragma unroll
        for (int i = 0; i < 16; i++) {
            int c = tid + i * 128;         // 0..2047
            int p = c >> 9;                // 0:kh 1:kl 2:vh 3:vl
            int r = (c >> 3) & 63, col16 = c & 7;
            const __nv_bfloat16* src = (p < 2 ? Kbh : Vbh)
                + (size_t)(p & 1) * NS * 64 + (size_t)(kv0 + r) * 64 + col16 * 8;
            uint32_t off = (uint32_t)(r * 128 + col16 * 16);
            cpasync16(sb + 32768 + buf * 32768 + p * 8192 + (off ^ ((off >> 3) & 0x70)), src);
        }
        asm volatile("cp.async.commit_group;" ::: "memory");
    };

    load_kv(0, 0);

    float m[2][2], l[2][2];
    #pragma unroll
    for (int a = 0; a < 2; a++)
        #pragma unroll
        for (int b = 0; b < 2; b++) { m[a][b] = -1e30f; l[a][b] = 0.f; }

    float o[2][8][4];
    #pragma unroll
    for (int a = 0; a < 2; a++)
        #pragma unroll
        for (int b = 0; b < 8; b++)
            #pragma unroll
            for (int c = 0; c < 4; c++) o[a][b][c] = 0.f;

    const int qw0 = qt * 128 + w * 32;   // warp's first q row
    const uint32_t qoff[3] = {0u, 16384u, 0u};
    const uint32_t koff[3] = {0u, 0u, 8192u};

    for (int kt = 0; kt < nkt; kt++) {
        if (kt + 1 < nkt) {
            load_kv(kt + 1, (kt + 1) & 1);
            asm volatile("cp.async.wait_group 1;" ::: "memory");
        } else {
            asm volatile("cp.async.wait_group 0;" ::: "memory");
        }
        __syncthreads();

        if (kt * 64 <= qw0 + 31) {   // warp has unmasked work in this tile
            const uint32_t sK = sb + 32768 + (uint32_t)(kt & 1) * 32768u;
            const uint32_t sV = sK + 16384u;

            // ---- S = QK^T (3 split passes) ----
            float s_[2][8][4];
            #pragma unroll
            for (int a = 0; a < 2; a++)
                #pragma unroll
                for (int b = 0; b < 8; b++)
                    #pragma unroll
                    for (int c = 0; c < 4; c++) s_[a][b][c] = 0.f;

            #pragma unroll
            for (int ps = 0; ps < 3; ps++) {
                #pragma unroll
                for (int ks = 0; ks < 4; ks++) {
                    uint32_t a[2][4];
                    #pragma unroll
                    for (int mi = 0; mi < 2; mi++) {
                        uint32_t off = (uint32_t)((w * 32 + mi * 16 + (lane & 15)) * 128
                                                  + (ks * 2 + (lane >> 4)) * 16);
                        ldsm4(a[mi], sb + qoff[ps] + (off ^ ((off >> 3) & 0x70)));
                    }
                    uint32_t bb[4][4];
                    #pragma unroll
                    for (int nj = 0; nj < 4; nj++) {
                        uint32_t off = (uint32_t)((nj * 16 + (lane & 15)) * 128
                                                  + (ks * 2 + (lane >> 4)) * 16);
                        ldsm4(bb[nj], sK + koff[ps] + (off ^ ((off >> 3) & 0x70)));
                    }
                    #pragma unroll
                    for (int mi = 0; mi < 2; mi++)
                        #pragma unroll
                        for (int ni = 0; ni < 8; ni++)
                            mma16816(s_[mi][ni], a[mi],
                                     bb[ni >> 1][ni & 1], bb[ni >> 1][2 + (ni & 1)]);
                }
            }

            // ---- causal mask ----
            if (kt * 64 + 63 > qw0) {
                #pragma unroll
                for (int mi = 0; mi < 2; mi++)
                    #pragma unroll
                    for (int ni = 0; ni < 8; ni++)
                        #pragma unroll
                        for (int c = 0; c < 4; c++) {
                            int qr = qw0 + mi * 16 + ((c >> 1) << 3) + (lane >> 2);
                            int kc = kt * 64 + ni * 8 + ((lane & 3) << 1) + (c & 1);
                            if (kc > qr) s_[mi][ni][c] = -1e30f;
                        }
            }

            // ---- online softmax (per row, quad reduce) ----
            #pragma unroll
            for (int mi = 0; mi < 2; mi++)
                #pragma unroll
                for (int rh = 0; rh < 2; rh++) {
                    float mx = -1e30f;
                    #pragma unroll
                    for (int ni = 0; ni < 8; ni++)
                        mx = fmaxf(mx, fmaxf(s_[mi][ni][rh*2], s_[mi][ni][rh*2+1]));
                    mx = fmaxf(mx, __shfl_xor_sync(0xffffffffu, mx, 1));
                    mx = fmaxf(mx, __shfl_xor_sync(0xffffffffu, mx, 2));
                    float mn = fmaxf(m[mi][rh], mx);
                    float sc = __expf(m[mi][rh] - mn);
                    m[mi][rh] = mn;
                    float sum = 0.f;
                    #pragma unroll
                    for (int ni = 0; ni < 8; ni++) {
                        float p0 = __expf(s_[mi][ni][rh*2]   - mn);
                        float p1 = __expf(s_[mi][ni][rh*2+1] - mn);
                        s_[mi][ni][rh*2] = p0; s_[mi][ni][rh*2+1] = p1;
                        sum += p0 + p1;
                    }
                    sum += __shfl_xor_sync(0xffffffffu, sum, 1);
                    sum += __shfl_xor_sync(0xffffffffu, sum, 2);
                    l[mi][rh] = l[mi][rh] * sc + sum;
                    #pragma unroll
                    for (int ni = 0; ni < 8; ni++) {
                        o[mi][ni][rh*2]   *= sc;
                        o[mi][ni][rh*2+1] *= sc;
                    }
                }

            // ---- O += P V (3 split passes, fused per k-step) ----
            #pragma unroll
            for (int ks = 0; ks < 4; ks++) {
                uint32_t ah[2][4], al[2][4];
                #pragma unroll
                for (int mi = 0; mi < 2; mi++) {
                    const float* t0 = s_[mi][2*ks];
                    const float* t1 = s_[mi][2*ks+1];
                    ah[mi][0] = packbf(t0[0], t0[1]);
                    ah[mi][1] = packbf(t0[2], t0[3]);
                    ah[mi][2] = packbf(t1[0], t1[1]);
                    ah[mi][3] = packbf(t1[2], t1[3]);
                    al[mi][0] = packlo(t0[0], t0[1], ah[mi][0]);
                    al[mi][1] = packlo(t0[2], t0[3], ah[mi][1]);
                    al[mi][2] = packlo(t1[0], t1[1], ah[mi][2]);
                    al[mi][3] = packlo(t1[2], t1[3], ah[mi][3]);
                }
                uint32_t bvh[4][4], bvl[4][4];
                #pragma unroll
                for (int nj = 0; nj < 4; nj++) {
                    uint32_t off = (uint32_t)((ks * 16 + (lane & 15)) * 128
                                              + (nj * 2 + (lane >> 4)) * 16);
                    off ^= (off >> 3) & 0x70;
                    ldsm4t(bvh[nj], sV + off);
                    ldsm4t(bvl[nj], sV + 8192 + off);
                }
                #pragma unroll
                for (int mi = 0; mi < 2; mi++)
                    #pragma unroll
                    for (int nd = 0; nd < 8; nd++) {
                        uint32_t b0 = bvh[nd >> 1][(nd & 1) * 2];
                        uint32_t b1 = bvh[nd >> 1][(nd & 1) * 2 + 1];
                        mma16816(o[mi][nd], ah[mi], b0, b1);
                        mma16816(o[mi][nd], al[mi], b0, b1);
                        uint32_t c0 = bvl[nd >> 1][(nd & 1) * 2];
                        uint32_t c1 = bvl[nd >> 1][(nd & 1) * 2 + 1];
                        mma16816(o[mi][nd], ah[mi], c0, c1);
                    }
            }
        }
        __syncthreads();
    }

    // ---- epilogue: O/l -> [B,S,D] fp32 ----
    const int b = bh >> 4, h = bh & 15;
    #pragma unroll
    for (int mi = 0; mi < 2; mi++)
        #pragma unroll
        for (int rh = 0; rh < 2; rh++) {
            float invl = 1.f / l[mi][rh];
            int row = qw0 + mi * 16 + rh * 8 + (lane >> 2);
            #pragma unroll
            for (int ni = 0; ni < 8; ni++) {
                float2 v = make_float2(o[mi][ni][rh*2] * invl, o[mi][ni][rh*2+1] * invl);
                *(float2*)(Og + (size_t)(b * NS + row) * ND + h * 64
                           + ni * 8 + ((lane & 3) << 1)) = v;
            }
        }
}

// ---------------------------------------------------------------------------
extern "C" void kernel_launch(void* const* d_in, const int* in_sizes, int n_in,
                              void* d_out, int out_size)
{
    const float* x  = (const float*)d_in[0];
    const float* Wq = (const float*)d_in[1];
    const float* Wk = (const float*)d_in[2];
    const float* Wv = (const float*)d_in[3];
    const float* Wo = (const float*)d_in[4];
    float* out = (float*)d_out;

    __nv_bfloat16 *xs, *as, *wq, *wk, *wv, *wo, *q, *k, *v;
    float *attn;
    cudaGetSymbolAddress((void**)&xs, g_xs);
    cudaGetSymbolAddress((void**)&as, g_as);
    cudaGetSymbolAddress((void**)&wq, g_wq);
    cudaGetSymbolAddress((void**)&wk, g_wk);
    cudaGetSymbolAddress((void**)&wv, g_wv);
    cudaGetSymbolAddress((void**)&wo, g_wo);
    cudaGetSymbolAddress((void**)&q,  g_q);
    cudaGetSymbolAddress((void**)&k,  g_k);
    cudaGetSymbolAddress((void**)&v,  g_v);
    cudaGetSymbolAddress((void**)&attn, g_attn);

    cudaFuncSetAttribute(gemm_mma<0>, cudaFuncAttributeMaxDynamicSharedMemorySize, GEMM_SMEM);
    cudaFuncSetAttribute(gemm_mma<1>, cudaFuncAttributeMaxDynamicSharedMemorySize, GEMM_SMEM);
    cudaFuncSetAttribute(gemm_mma<2>, cudaFuncAttributeMaxDynamicSharedMemorySize, GEMM_SMEM);
    cudaFuncSetAttribute(fattn, cudaFuncAttributeMaxDynamicSharedMemorySize, ATTN_SMEM);

    {
        int tx = MROWS * (ND / 2);
        split_bf16<1><<<(tx + 255) / 256, 256>>>(x, xs, MROWS);
        int tw = ND * (ND / 2);
        split_bf16<0><<<(tw + 255) / 256, 256>>>(Wq, wq, ND);
        split_bf16<0><<<(tw + 255) / 256, 256>>>(Wk, wk, ND);
        split_bf16<0><<<(tw + 255) / 256, 256>>>(Wv, wv, ND);
        split_bf16<0><<<(tw + 255) / 256, 256>>>(Wo, wo, ND);
    }

    dim3 gGrid(ND / 128, MROWS / 128);  // (8, 64)
    gemm_mma<2><<<gGrid, 256, GEMM_SMEM>>>(xs, wq, q);   // Q, pre-scaled 1/8
    gemm_mma<1><<<gGrid, 256, GEMM_SMEM>>>(xs, wk, k);
    gemm_mma<1><<<gGrid, 256, GEMM_SMEM>>>(xs, wv, v);

    fattn<<<dim3(NB * NH, NS / 128), 128, ATTN_SMEM>>>(q, k, v, attn);

    {
        int tx = MROWS * (ND / 2);
        split_bf16<1><<<(tx + 255) / 256, 256>>>(attn, as, MROWS);
    }
    gemm_mma<0><<<gGrid, 256, GEMM_SMEM>>>(as, wo, out);
}

// round 5
// speedup vs baseline: 4.6730x; 1.3177x over previous
#include <cuda_runtime.h>
#include <cuda_bf16.h>
#include <cstdint>

#define NB 4
#define NS 2048
#define ND 1024
#define NH 16
#define DKH 64
#define MROWS (NB*NS)   // 8192
#define KX 3072         // split-extended K (3 blocks of 1024)

// ---------------- scratch (__device__ globals; no allocation) ----------------
__device__ __nv_bfloat16 g_xs[(size_t)MROWS * KX];    // x split    [hi,lo,hi]
__device__ __nv_bfloat16 g_as[(size_t)MROWS * KX];    // attn split [hi,lo,hi]
__device__ __nv_bfloat16 g_wqkv[(size_t)3 * ND * KX]; // Wq|Wk|Wv split [hi,hi,lo]
__device__ __nv_bfloat16 g_wo[(size_t)ND * KX];
// split-bf16 Q/K/V: [bh][plane(hi=0,lo=1)][S][64]
__device__ __nv_bfloat16 g_q[(size_t)NB*NH*2*NS*DKH];
__device__ __nv_bfloat16 g_k[(size_t)NB*NH*2*NS*DKH];
__device__ __nv_bfloat16 g_v[(size_t)NB*NH*2*NS*DKH];
__device__ float g_attn[(size_t)MROWS * ND];          // [B,S,D] pre-Wo

// ---------------- helpers ----------------
__device__ __forceinline__ uint32_t smem_u32(const void* p) {
    uint32_t a;
    asm("{ .reg .u64 t; cvta.to.shared.u64 t, %1; cvt.u32.u64 %0, t; }" : "=r"(a) : "l"(p));
    return a;
}
__device__ __forceinline__ void ldsm4(uint32_t* r, uint32_t addr) {
    asm volatile("ldmatrix.sync.aligned.m8n8.x4.shared.b16 {%0,%1,%2,%3}, [%4];"
                 : "=r"(r[0]), "=r"(r[1]), "=r"(r[2]), "=r"(r[3]) : "r"(addr));
}
__device__ __forceinline__ void ldsm4t(uint32_t* r, uint32_t addr) {
    asm volatile("ldmatrix.sync.aligned.m8n8.x4.trans.shared.b16 {%0,%1,%2,%3}, [%4];"
                 : "=r"(r[0]), "=r"(r[1]), "=r"(r[2]), "=r"(r[3]) : "r"(addr));
}
__device__ __forceinline__ void mma16816(float* c, const uint32_t* a, uint32_t b0, uint32_t b1) {
    asm volatile("mma.sync.aligned.m16n8k16.row.col.f32.bf16.bf16.f32 "
                 "{%0,%1,%2,%3}, {%4,%5,%6,%7}, {%8,%9}, {%0,%1,%2,%3};"
                 : "+f"(c[0]), "+f"(c[1]), "+f"(c[2]), "+f"(c[3])
                 : "r"(a[0]), "r"(a[1]), "r"(a[2]), "r"(a[3]), "r"(b0), "r"(b1));
}
__device__ __forceinline__ void cpasync16(uint32_t dst, const void* src) {
    asm volatile("cp.async.cg.shared.global [%0], [%1], 16;" :: "r"(dst), "l"(src));
}
__device__ __forceinline__ void cp_commit() {
    asm volatile("cp.async.commit_group;" ::: "memory");
}
__device__ __forceinline__ uint32_t packbf(float a, float b) {
    __nv_bfloat162 h = __floats2bfloat162_rn(a, b);
    return *(uint32_t*)&h;
}
__device__ __forceinline__ uint32_t packlo(float a, float b, uint32_t hbits) {
    __nv_bfloat162 h = *(__nv_bfloat162*)&hbits;
    return packbf(a - __bfloat162float(h.x), b - __bfloat162float(h.y));
}

// ---------------- fp32 -> split-bf16 conversion ----------------
// AMODE=1: blocks [hi, lo, hi] (activations)   AMODE=0: [hi, hi, lo] (weights)
template<int AMODE>
__global__ void split_bf16(const float* __restrict__ src, __nv_bfloat16* __restrict__ dst,
                           int rows)
{
    int i = blockIdx.x * blockDim.x + threadIdx.x;
    int total = rows * (ND / 2);
    if (i >= total) return;
    int r  = i >> 9;
    int cp = i & 511;
    float2 v = *(const float2*)(src + (size_t)r * ND + cp * 2);
    __nv_bfloat16 h0 = __float2bfloat16(v.x);
    __nv_bfloat16 h1 = __float2bfloat16(v.y);
    __nv_bfloat16 l0 = __float2bfloat16(v.x - __bfloat162float(h0));
    __nv_bfloat16 l1 = __float2bfloat16(v.y - __bfloat162float(h1));
    __nv_bfloat162 hh; hh.x = h0; hh.y = h1;
    __nv_bfloat162 ll; ll.x = l0; ll.y = l1;
    __nv_bfloat162* d2 = (__nv_bfloat162*)(dst + (size_t)r * KX) + cp;
    d2[0]    = hh;
    d2[512]  = AMODE ? ll : hh;
    d2[1024] = AMODE ? hh : ll;
}

// ---------------- HMMA bf16 NT GEMM, 3-stage cp.async pipeline ----------------
// C[m,n] = sum_k A[m,k]*B[n,k]. CTA tile 128x128, BK=64, 256 thr, 8 warps 2x4.
// OMODE 0: fp32 out [M,ND] (Wo).  OMODE 1: merged QKV -> split-bf16 head layout
// (n<1024: Q scaled by 0.125; n<2048: K; else V).
static constexpr int GEMM_NT    = KX / 64;   // 48 K-tiles
static constexpr int GEMM_SMEM  = 3 * 32768; // 98304 (3 stages)

__device__ __forceinline__ void gemm_cp(const __nv_bfloat16* __restrict__ A,
                                        const __nv_bfloat16* __restrict__ Bw,
                                        int m0, int n0, int k0,
                                        uint32_t sbuf, int tid)
{
    #pragma unroll
    for (int i = 0; i < 8; i++) {
        int c = tid + i * 256;           // 0..2047 16B chunks
        int r = (c >> 3) & 127;
        int col16 = c & 7;
        const __nv_bfloat16* src = (c < 1024)
            ? A  + (size_t)(m0 + r) * KX + k0 + col16 * 8
            : Bw + (size_t)(n0 + r) * KX + k0 + col16 * 8;
        uint32_t off = (uint32_t)(r * 128 + col16 * 16);
        off ^= (off >> 3) & 0x70;
        cpasync16(sbuf + (c < 1024 ? 0u : 16384u) + off, src);
    }
}

template<int OMODE>
__global__ void __launch_bounds__(256)
gemm_mma(const __nv_bfloat16* __restrict__ A, const __nv_bfloat16* __restrict__ Bw,
         float* __restrict__ outF,
         __nv_bfloat16* __restrict__ qp, __nv_bfloat16* __restrict__ kp,
         __nv_bfloat16* __restrict__ vp)
{
    extern __shared__ __align__(1024) char smem[];
    const int tid  = threadIdx.x;
    const int lane = tid & 31;
    const int wid  = tid >> 5;
    const int warp_m = wid & 1;
    const int warp_n = wid >> 1;
    const int m0 = blockIdx.y * 128;
    const int n0 = blockIdx.x * 128;

    const uint32_t sbase = smem_u32(smem);
    const int qrow = lane & 15;
    const int qcol = lane >> 4;

    float acc[4][4][4];
    #pragma unroll
    for (int a = 0; a < 4; a++)
        #pragma unroll
        for (int b = 0; b < 4; b++)
            #pragma unroll
            for (int c = 0; c < 4; c++) acc[a][b][c] = 0.f;

    // prologue: stages 0,1
    gemm_cp(A, Bw, m0, n0, 0,  sbase,          tid); cp_commit();
    gemm_cp(A, Bw, m0, n0, 64, sbase + 32768u, tid); cp_commit();

    int buf_c = 0;   // t % 3
    int buf_i = 2;   // (t+2) % 3
    #pragma unroll 1
    for (int t = 0; t < GEMM_NT; t++) {
        asm volatile("cp.async.wait_group 1;" ::: "memory");
        __syncthreads();
        if (t + 2 < GEMM_NT)
            gemm_cp(A, Bw, m0, n0, (t + 2) * 64, sbase + (uint32_t)buf_i * 32768u, tid);
        cp_commit();

        const uint32_t sA = sbase + (uint32_t)buf_c * 32768u;
        const uint32_t sB = sA + 16384u;

        #pragma unroll
        for (int ks = 0; ks < 4; ks++) {
            uint32_t afr[4][4], bfr[2][4];
            #pragma unroll
            for (int mi = 0; mi < 4; mi++) {
                uint32_t off = (uint32_t)((warp_m * 64 + mi * 16 + qrow) * 128
                                          + (ks * 2 + qcol) * 16);
                ldsm4(afr[mi], sA + (off ^ ((off >> 3) & 0x70)));
            }
            #pragma unroll
            for (int nj = 0; nj < 2; nj++) {
                uint32_t off = (uint32_t)((warp_n * 32 + nj * 16 + qrow) * 128
                                          + (ks * 2 + qcol) * 16);
                ldsm4(bfr[nj], sB + (off ^ ((off >> 3) & 0x70)));
            }
            #pragma unroll
            for (int mi = 0; mi < 4; mi++)
                #pragma unroll
                for (int ni = 0; ni < 4; ni++)
                    mma16816(acc[mi][ni], afr[mi],
                             bfr[ni >> 1][ni & 1], bfr[ni >> 1][2 + (ni & 1)]);
        }

        buf_c = (buf_c == 2) ? 0 : buf_c + 1;
        buf_i = (buf_i == 2) ? 0 : buf_i + 1;
        __syncthreads();
    }

    const int tr = lane >> 2;
    const int tc = (lane & 3) * 2;
    const int which = n0 >> 10;                 // 0:Q 1:K 2:V (OMODE 1)
    const float scale = (OMODE == 1 && which == 0) ? 0.125f : 1.f;
    __nv_bfloat16* hdst = (which == 0) ? qp : (which == 1) ? kp : vp;
    const int ncol0 = n0 & 1023;

    #pragma unroll
    for (int mi = 0; mi < 4; mi++) {
        #pragma unroll
        for (int ni = 0; ni < 4; ni++) {
            const int row = m0 + warp_m * 64 + mi * 16 + tr;
            const int col = (OMODE ? ncol0 : n0) + warp_n * 32 + ni * 8 + tc;
            float* cc = acc[mi][ni];
            #pragma unroll
            for (int half = 0; half < 2; half++) {
                const int r = row + half * 8;
                float2 val = half ? make_float2(cc[2], cc[3]) : make_float2(cc[0], cc[1]);
                if (OMODE == 0) {
                    *(float2*)(outF + (size_t)r * ND + col) = val;
                } else {
                    val.x *= scale; val.y *= scale;
                    const int b = r >> 11, s = r & (NS - 1);
                    const int h = col >> 6, ch = col & 63;
                    __nv_bfloat162 hi = __floats2bfloat162_rn(val.x, val.y);
                    __nv_bfloat162 lo = __floats2bfloat162_rn(
                        val.x - __bfloat162float(hi.x), val.y - __bfloat162float(hi.y));
                    __nv_bfloat16* base = hdst
                        + (((size_t)(b * NH + h) * 2) * NS + s) * 64 + ch;
                    *(__nv_bfloat162*)base           = hi;
                    *(__nv_bfloat162*)(base + NS*64) = lo;
                }
            }
        }
    }
}

// ---------------------------------------------------------------------------
// HMMA causal flash attention. CTA = (bh, 128 q-rows). 4 warps x 32 rows.
// QK^T 3 passes (qh*kh + ql*kh + qh*kl); softmax fp32; PV 3 passes
// (ph*vh + pl*vh + ph*vl). kv tiles of 64 double-buffered via cp.async.
// smem: Q 2x16KB | 2 bufs x (Kh,Kl,Vh,Vl) 4x8KB  = 96KB.
// ---------------------------------------------------------------------------
static constexpr int ATTN_SMEM = 32768 + 2 * 32768;  // 98304

__global__ void __launch_bounds__(128)
fattn(const __nv_bfloat16* __restrict__ Qg, const __nv_bfloat16* __restrict__ Kg,
      const __nv_bfloat16* __restrict__ Vg, float* __restrict__ Og)
{
    extern __shared__ __align__(1024) char sm[];
    const uint32_t sb = smem_u32(sm);
    const int bh  = blockIdx.x;
    const int qt  = (int)gridDim.y - 1 - (int)blockIdx.y;  // big tiles first
    const int tid = threadIdx.x, lane = tid & 31, w = tid >> 5;

    const __nv_bfloat16* Qbh = Qg + (size_t)bh * 2 * NS * 64;
    const __nv_bfloat16* Kbh = Kg + (size_t)bh * 2 * NS * 64;
    const __nv_bfloat16* Vbh = Vg + (size_t)bh * 2 * NS * 64;

    #pragma unroll
    for (int i = 0; i < 16; i++) {
        int c = tid + i * 128;
        int p = c >> 10, r = (c >> 3) & 127, col16 = c & 7;
        uint4 v = *(const uint4*)(Qbh + (size_t)p * NS * 64
                                  + (size_t)(qt * 128 + r) * 64 + col16 * 8);
        uint32_t off = (uint32_t)(r * 128 + col16 * 16);
        *(uint4*)(sm + p * 16384 + (off ^ ((off >> 3) & 0x70))) = v;
    }

    const int nkt = 2 * qt + 2;

    auto load_kv = [&](int kt, int buf) {
        const int kv0 = kt * 64;
        #pragma unroll
        for (int i = 0; i < 16; i++) {
            int c = tid + i * 128;
            int p = c >> 9;
            int r = (c >> 3) & 63, col16 = c & 7;
            const __nv_bfloat16* src = (p < 2 ? Kbh : Vbh)
                + (size_t)(p & 1) * NS * 64 + (size_t)(kv0 + r) * 64 + col16 * 8;
            uint32_t off = (uint32_t)(r * 128 + col16 * 16);
            cpasync16(sb + 32768 + buf * 32768 + p * 8192 + (off ^ ((off >> 3) & 0x70)), src);
        }
        cp_commit();
    };

    load_kv(0, 0);

    float m[2][2], l[2][2];
    #pragma unroll
    for (int a = 0; a < 2; a++)
        #pragma unroll
        for (int b = 0; b < 2; b++) { m[a][b] = -1e30f; l[a][b] = 0.f; }

    float o[2][8][4];
    #pragma unroll
    for (int a = 0; a < 2; a++)
        #pragma unroll
        for (int b = 0; b < 8; b++)
            #pragma unroll
            for (int c = 0; c < 4; c++) o[a][b][c] = 0.f;

    const int qw0 = qt * 128 + w * 32;
    const uint32_t qoff[3] = {0u, 16384u, 0u};
    const uint32_t koff[3] = {0u, 0u, 8192u};

    for (int kt = 0; kt < nkt; kt++) {
        if (kt + 1 < nkt) {
            load_kv(kt + 1, (kt + 1) & 1);
            asm volatile("cp.async.wait_group 1;" ::: "memory");
        } else {
            asm volatile("cp.async.wait_group 0;" ::: "memory");
        }
        __syncthreads();

        if (kt * 64 <= qw0 + 31) {
            const uint32_t sK = sb + 32768 + (uint32_t)(kt & 1) * 32768u;
            const uint32_t sV = sK + 16384u;

            float s_[2][8][4];
            #pragma unroll
            for (int a = 0; a < 2; a++)
                #pragma unroll
                for (int b = 0; b < 8; b++)
                    #pragma unroll
                    for (int c = 0; c < 4; c++) s_[a][b][c] = 0.f;

            #pragma unroll
            for (int ps = 0; ps < 3; ps++) {
                #pragma unroll
                for (int ks = 0; ks < 4; ks++) {
                    uint32_t a[2][4];
                    #pragma unroll
                    for (int mi = 0; mi < 2; mi++) {
                        uint32_t off = (uint32_t)((w * 32 + mi * 16 + (lane & 15)) * 128
                                                  + (ks * 2 + (lane >> 4)) * 16);
                        ldsm4(a[mi], sb + qoff[ps] + (off ^ ((off >> 3) & 0x70)));
                    }
                    uint32_t bb[4][4];
                    #pragma unroll
                    for (int nj = 0; nj < 4; nj++) {
                        uint32_t off = (uint32_t)((nj * 16 + (lane & 15)) * 128
                                                  + (ks * 2 + (lane >> 4)) * 16);
                        ldsm4(bb[nj], sK + koff[ps] + (off ^ ((off >> 3) & 0x70)));
                    }
                    #pragma unroll
                    for (int mi = 0; mi < 2; mi++)
                        #pragma unroll
                        for (int ni = 0; ni < 8; ni++)
                            mma16816(s_[mi][ni], a[mi],
                                     bb[ni >> 1][ni & 1], bb[ni >> 1][2 + (ni & 1)]);
                }
            }

            if (kt * 64 + 63 > qw0) {
                #pragma unroll
                for (int mi = 0; mi < 2; mi++)
                    #pragma unroll
                    for (int ni = 0; ni < 8; ni++)
                        #pragma unroll
                        for (int c = 0; c < 4; c++) {
                            int qr = qw0 + mi * 16 + ((c >> 1) << 3) + (lane >> 2);
                            int kc = kt * 64 + ni * 8 + ((lane & 3) << 1) + (c & 1);
                            if (kc > qr) s_[mi][ni][c] = -1e30f;
                        }
            }

            #pragma unroll
            for (int mi = 0; mi < 2; mi++)
                #pragma unroll
                for (int rh = 0; rh < 2; rh++) {
                    float mx = -1e30f;
                    #pragma unroll
                    for (int ni = 0; ni < 8; ni++)
                        mx = fmaxf(mx, fmaxf(s_[mi][ni][rh*2], s_[mi][ni][rh*2+1]));
                    mx = fmaxf(mx, __shfl_xor_sync(0xffffffffu, mx, 1));
                    mx = fmaxf(mx, __shfl_xor_sync(0xffffffffu, mx, 2));
                    float mn = fmaxf(m[mi][rh], mx);
                    float sc = __expf(m[mi][rh] - mn);
                    m[mi][rh] = mn;
                    float sum = 0.f;
                    #pragma unroll
                    for (int ni = 0; ni < 8; ni++) {
                        float p0 = __expf(s_[mi][ni][rh*2]   - mn);
                        float p1 = __expf(s_[mi][ni][rh*2+1] - mn);
                        s_[mi][ni][rh*2] = p0; s_[mi][ni][rh*2+1] = p1;
                        sum += p0 + p1;
                    }
                    sum += __shfl_xor_sync(0xffffffffu, sum, 1);
                    sum += __shfl_xor_sync(0xffffffffu, sum, 2);
                    l[mi][rh] = l[mi][rh] * sc + sum;
                    #pragma unroll
                    for (int ni = 0; ni < 8; ni++) {
                        o[mi][ni][rh*2]   *= sc;
                        o[mi][ni][rh*2+1] *= sc;
                    }
                }

            #pragma unroll
            for (int ks = 0; ks < 4; ks++) {
                uint32_t ah[2][4], al[2][4];
                #pragma unroll
                for (int mi = 0; mi < 2; mi++) {
                    const float* t0 = s_[mi][2*ks];
                    const float* t1 = s_[mi][2*ks+1];
                    ah[mi][0] = packbf(t0[0], t0[1]);
                    ah[mi][1] = packbf(t0[2], t0[3]);
                    ah[mi][2] = packbf(t1[0], t1[1]);
                    ah[mi][3] = packbf(t1[2], t1[3]);
                    al[mi][0] = packlo(t0[0], t0[1], ah[mi][0]);
                    al[mi][1] = packlo(t0[2], t0[3], ah[mi][1]);
                    al[mi][2] = packlo(t1[0], t1[1], ah[mi][2]);
                    al[mi][3] = packlo(t1[2], t1[3], ah[mi][3]);
                }
                uint32_t bvh[4][4], bvl[4][4];
                #pragma unroll
                for (int nj = 0; nj < 4; nj++) {
                    uint32_t off = (uint32_t)((ks * 16 + (lane & 15)) * 128
                                              + (nj * 2 + (lane >> 4)) * 16);
                    off ^= (off >> 3) & 0x70;
                    ldsm4t(bvh[nj], sV + off);
                    ldsm4t(bvl[nj], sV + 8192 + off);
                }
                #pragma unroll
                for (int mi = 0; mi < 2; mi++)
                    #pragma unroll
                    for (int nd = 0; nd < 8; nd++) {
                        uint32_t b0 = bvh[nd >> 1][(nd & 1) * 2];
                        uint32_t b1 = bvh[nd >> 1][(nd & 1) * 2 + 1];
                        mma16816(o[mi][nd], ah[mi], b0, b1);
                        mma16816(o[mi][nd], al[mi], b0, b1);
                        uint32_t c0 = bvl[nd >> 1][(nd & 1) * 2];
                        uint32_t c1 = bvl[nd >> 1][(nd & 1) * 2 + 1];
                        mma16816(o[mi][nd], ah[mi], c0, c1);
                    }
            }
        }
        __syncthreads();
    }

    const int b = bh >> 4, h = bh & 15;
    #pragma unroll
    for (int mi = 0; mi < 2; mi++)
        #pragma unroll
        for (int rh = 0; rh < 2; rh++) {
            float invl = 1.f / l[mi][rh];
            int row = qw0 + mi * 16 + rh * 8 + (lane >> 2);
            #pragma unroll
            for (int ni = 0; ni < 8; ni++) {
                float2 v = make_float2(o[mi][ni][rh*2] * invl, o[mi][ni][rh*2+1] * invl);
                *(float2*)(Og + (size_t)(b * NS + row) * ND + h * 64
                           + ni * 8 + ((lane & 3) << 1)) = v;
            }
        }
}

// ---------------------------------------------------------------------------
extern "C" void kernel_launch(void* const* d_in, const int* in_sizes, int n_in,
                              void* d_out, int out_size)
{
    const float* x  = (const float*)d_in[0];
    const float* Wq = (const float*)d_in[1];
    const float* Wk = (const float*)d_in[2];
    const float* Wv = (const float*)d_in[3];
    const float* Wo = (const float*)d_in[4];
    float* out = (float*)d_out;

    __nv_bfloat16 *xs, *as, *wqkv, *wo, *q, *k, *v;
    float *attn;
    cudaGetSymbolAddress((void**)&xs,   g_xs);
    cudaGetSymbolAddress((void**)&as,   g_as);
    cudaGetSymbolAddress((void**)&wqkv, g_wqkv);
    cudaGetSymbolAddress((void**)&wo,   g_wo);
    cudaGetSymbolAddress((void**)&q,    g_q);
    cudaGetSymbolAddress((void**)&k,    g_k);
    cudaGetSymbolAddress((void**)&v,    g_v);
    cudaGetSymbolAddress((void**)&attn, g_attn);

    cudaFuncSetAttribute(gemm_mma<0>, cudaFuncAttributeMaxDynamicSharedMemorySize, GEMM_SMEM);
    cudaFuncSetAttribute(gemm_mma<1>, cudaFuncAttributeMaxDynamicSharedMemorySize, GEMM_SMEM);
    cudaFuncSetAttribute(fattn, cudaFuncAttributeMaxDynamicSharedMemorySize, ATTN_SMEM);

    {
        int tx = MROWS * (ND / 2);
        split_bf16<1><<<(tx + 255) / 256, 256>>>(x, xs, MROWS);
        int tw = ND * (ND / 2);
        split_bf16<0><<<(tw + 255) / 256, 256>>>(Wq, wqkv,                     ND);
        split_bf16<0><<<(tw + 255) / 256, 256>>>(Wk, wqkv + (size_t)ND * KX,   ND);
        split_bf16<0><<<(tw + 255) / 256, 256>>>(Wv, wqkv + (size_t)2*ND * KX, ND);
        split_bf16<0><<<(tw + 255) / 256, 256>>>(Wo, wo,                       ND);
    }

    // fused QKV projection: N = 3072
    gemm_mma<1><<<dim3(3 * ND / 128, MROWS / 128), 256, GEMM_SMEM>>>(
        xs, wqkv, nullptr, q, k, v);

    fattn<<<dim3(NB * NH, NS / 128), 128, ATTN_SMEM>>>(q, k, v, attn);

    {
        int tx = MROWS * (ND / 2);
        split_bf16<1><<<(tx + 255) / 256, 256>>>(attn, as, MROWS);
    }
    gemm_mma<0><<<dim3(ND / 128, MROWS / 128), 256, GEMM_SMEM>>>(
        as, wo, out, nullptr, nullptr, nullptr);
}

// round 6
// speedup vs baseline: 5.2296x; 1.1191x over previous
#include <cuda_runtime.h>
#include <cuda_bf16.h>
#include <cstdint>

#define NB 4
#define NS 2048
#define ND 1024
#define NH 16
#define DKH 64
#define MROWS (NB*NS)   // 8192
#define KX 3072         // split-extended K (3 blocks of 1024)

// ---------------- scratch (__device__ globals; no allocation) ----------------
__device__ __nv_bfloat16 g_xs[(size_t)MROWS * KX];    // x split    [hi,lo,hi]
__device__ __nv_bfloat16 g_as[(size_t)MROWS * KX];    // attn split [hi,lo,hi]
__device__ __nv_bfloat16 g_wqkv[(size_t)3 * ND * KX]; // Wq|Wk|Wv split [hi,hi,lo]
__device__ __nv_bfloat16 g_wo[(size_t)ND * KX];
// split-bf16 Q/K/V: [bh][plane(hi=0,lo=1)][S][64]
__device__ __nv_bfloat16 g_q[(size_t)NB*NH*2*NS*DKH];
__device__ __nv_bfloat16 g_k[(size_t)NB*NH*2*NS*DKH];
__device__ __nv_bfloat16 g_v[(size_t)NB*NH*2*NS*DKH];

// ---------------- helpers ----------------
__device__ __forceinline__ uint32_t smem_u32(const void* p) {
    uint32_t a;
    asm("{ .reg .u64 t; cvta.to.shared.u64 t, %1; cvt.u32.u64 %0, t; }" : "=r"(a) : "l"(p));
    return a;
}
__device__ __forceinline__ void ldsm4(uint32_t* r, uint32_t addr) {
    asm volatile("ldmatrix.sync.aligned.m8n8.x4.shared.b16 {%0,%1,%2,%3}, [%4];"
                 : "=r"(r[0]), "=r"(r[1]), "=r"(r[2]), "=r"(r[3]) : "r"(addr));
}
__device__ __forceinline__ void ldsm4t(uint32_t* r, uint32_t addr) {
    asm volatile("ldmatrix.sync.aligned.m8n8.x4.trans.shared.b16 {%0,%1,%2,%3}, [%4];"
                 : "=r"(r[0]), "=r"(r[1]), "=r"(r[2]), "=r"(r[3]) : "r"(addr));
}
__device__ __forceinline__ void mma16816(float* c, const uint32_t* a, uint32_t b0, uint32_t b1) {
    asm volatile("mma.sync.aligned.m16n8k16.row.col.f32.bf16.bf16.f32 "
                 "{%0,%1,%2,%3}, {%4,%5,%6,%7}, {%8,%9}, {%0,%1,%2,%3};"
                 : "+f"(c[0]), "+f"(c[1]), "+f"(c[2]), "+f"(c[3])
                 : "r"(a[0]), "r"(a[1]), "r"(a[2]), "r"(a[3]), "r"(b0), "r"(b1));
}
__device__ __forceinline__ void cpasync16(uint32_t dst, const void* src) {
    asm volatile("cp.async.cg.shared.global [%0], [%1], 16;" :: "r"(dst), "l"(src));
}
__device__ __forceinline__ void cp_commit() {
    asm volatile("cp.async.commit_group;" ::: "memory");
}
__device__ __forceinline__ uint32_t packbf(float a, float b) {
    __nv_bfloat162 h = __floats2bfloat162_rn(a, b);
    return *(uint32_t*)&h;
}
__device__ __forceinline__ uint32_t packlo(float a, float b, uint32_t hbits) {
    __nv_bfloat162 h = *(__nv_bfloat162*)&hbits;
    return packbf(a - __bfloat162float(h.x), b - __bfloat162float(h.y));
}

// ---------------- fp32 -> split-bf16 conversions ----------------
// activations: blocks [hi, lo, hi]
__global__ void split_act(const float* __restrict__ src, __nv_bfloat16* __restrict__ dst)
{
    int i = blockIdx.x * blockDim.x + threadIdx.x;
    int r  = i >> 9;
    int cp = i & 511;
    float2 v = *(const float2*)(src + (size_t)r * ND + cp * 2);
    __nv_bfloat162 hh = __floats2bfloat162_rn(v.x, v.y);
    __nv_bfloat162 ll = __floats2bfloat162_rn(v.x - __bfloat162float(hh.x),
                                              v.y - __bfloat162float(hh.y));
    __nv_bfloat162* d2 = (__nv_bfloat162*)(dst + (size_t)r * KX) + cp;
    d2[0]    = hh;
    d2[512]  = ll;
    d2[1024] = hh;
}
// all four weights in one launch: blocks [hi, hi, lo]; grid.y picks the matrix
__global__ void split_w(const float* __restrict__ Wq, const float* __restrict__ Wk,
                        const float* __restrict__ Wv, const float* __restrict__ Wo,
                        __nv_bfloat16* __restrict__ wqkv, __nv_bfloat16* __restrict__ wo)
{
    int which = blockIdx.y;
    const float* src = (which == 0) ? Wq : (which == 1) ? Wk : (which == 2) ? Wv : Wo;
    __nv_bfloat16* dst = (which == 3) ? wo : wqkv + (size_t)which * ND * KX;
    int i = blockIdx.x * blockDim.x + threadIdx.x;
    int r  = i >> 9;
    int cp = i & 511;
    float2 v = *(const float2*)(src + (size_t)r * ND + cp * 2);
    __nv_bfloat162 hh = __floats2bfloat162_rn(v.x, v.y);
    __nv_bfloat162 ll = __floats2bfloat162_rn(v.x - __bfloat162float(hh.x),
                                              v.y - __bfloat162float(hh.y));
    __nv_bfloat162* d2 = (__nv_bfloat162*)(dst + (size_t)r * KX) + cp;
    d2[0]    = hh;
    d2[512]  = hh;
    d2[1024] = ll;
}

// ---------------- HMMA bf16 NT GEMM, 3-stage cp.async, 64x64 warp tiles ------
// C[m,n] = sum_k A[m,k]*B[n,k]. CTA 128x128, BK=64, 128 thr = 4 warps (2m x 2n).
// OMODE 0: fp32 out [M,ND] (Wo).  OMODE 1: merged QKV -> split-bf16 head layout.
static constexpr int GEMM_NT    = KX / 64;   // 48 K-tiles
static constexpr int GEMM_SMEM  = 3 * 32768; // 98304 (3 stages)

__device__ __forceinline__ void gemm_cp(const __nv_bfloat16* __restrict__ A,
                                        const __nv_bfloat16* __restrict__ Bw,
                                        int m0, int n0, int k0,
                                        uint32_t sbuf, int tid)
{
    #pragma unroll
    for (int i = 0; i < 16; i++) {
        int c = tid + i * 128;           // 0..2047 16B chunks
        int r = (c >> 3) & 127;
        int col16 = c & 7;
        const __nv_bfloat16* src = (c < 1024)
            ? A  + (size_t)(m0 + r) * KX + k0 + col16 * 8
            : Bw + (size_t)(n0 + r) * KX + k0 + col16 * 8;
        uint32_t off = (uint32_t)(r * 128 + col16 * 16);
        off ^= (off >> 3) & 0x70;
        cpasync16(sbuf + (c < 1024 ? 0u : 16384u) + off, src);
    }
}

template<int OMODE>
__global__ void __launch_bounds__(128, 2)
gemm_mma(const __nv_bfloat16* __restrict__ A, const __nv_bfloat16* __restrict__ Bw,
         float* __restrict__ outF,
         __nv_bfloat16* __restrict__ qp, __nv_bfloat16* __restrict__ kp,
         __nv_bfloat16* __restrict__ vp)
{
    extern __shared__ __align__(1024) char smem[];
    const int tid  = threadIdx.x;
    const int lane = tid & 31;
    const int wid  = tid >> 5;
    const int warp_m = wid & 1;    // 2 x 64 rows
    const int warp_n = wid >> 1;   // 2 x 64 cols
    const int m0 = blockIdx.y * 128;
    const int n0 = blockIdx.x * 128;

    const uint32_t sbase = smem_u32(smem);
    const int qrow = lane & 15;
    const int qcol = lane >> 4;

    float acc[4][8][4];
    #pragma unroll
    for (int a = 0; a < 4; a++)
        #pragma unroll
        for (int b = 0; b < 8; b++)
            #pragma unroll
            for (int c = 0; c < 4; c++) acc[a][b][c] = 0.f;

    gemm_cp(A, Bw, m0, n0, 0,  sbase,          tid); cp_commit();
    gemm_cp(A, Bw, m0, n0, 64, sbase + 32768u, tid); cp_commit();

    int buf_c = 0;
    int buf_i = 2;
    #pragma unroll 1
    for (int t = 0; t < GEMM_NT; t++) {
        asm volatile("cp.async.wait_group 1;" ::: "memory");
        __syncthreads();
        if (t + 2 < GEMM_NT)
            gemm_cp(A, Bw, m0, n0, (t + 2) * 64, sbase + (uint32_t)buf_i * 32768u, tid);
        cp_commit();

        const uint32_t sA = sbase + (uint32_t)buf_c * 32768u;
        const uint32_t sB = sA + 16384u;

        #pragma unroll
        for (int ks = 0; ks < 4; ks++) {
            uint32_t afr[4][4], bfr[4][4];
            #pragma unroll
            for (int mi = 0; mi < 4; mi++) {
                uint32_t off = (uint32_t)((warp_m * 64 + mi * 16 + qrow) * 128
                                          + (ks * 2 + qcol) * 16);
                ldsm4(afr[mi], sA + (off ^ ((off >> 3) & 0x70)));
            }
            #pragma unroll
            for (int nj = 0; nj < 4; nj++) {
                uint32_t off = (uint32_t)((warp_n * 64 + nj * 16 + qrow) * 128
                                          + (ks * 2 + qcol) * 16);
                ldsm4(bfr[nj], sB + (off ^ ((off >> 3) & 0x70)));
            }
            #pragma unroll
            for (int mi = 0; mi < 4; mi++)
                #pragma unroll
                for (int ni = 0; ni < 8; ni++)
                    mma16816(acc[mi][ni], afr[mi],
                             bfr[ni >> 1][ni & 1], bfr[ni >> 1][2 + (ni & 1)]);
        }

        buf_c = (buf_c == 2) ? 0 : buf_c + 1;
        buf_i = (buf_i == 2) ? 0 : buf_i + 1;
        __syncthreads();
    }

    const int tr = lane >> 2;
    const int tc = (lane & 3) * 2;
    const int which = n0 >> 10;                 // 0:Q 1:K 2:V (OMODE 1)
    const float scale = (OMODE == 1 && which == 0) ? 0.125f : 1.f;
    __nv_bfloat16* hdst = (which == 0) ? qp : (which == 1) ? kp : vp;
    const int ncol0 = n0 & 1023;

    #pragma unroll
    for (int mi = 0; mi < 4; mi++) {
        #pragma unroll
        for (int ni = 0; ni < 8; ni++) {
            const int row = m0 + warp_m * 64 + mi * 16 + tr;
            const int col = (OMODE ? ncol0 : n0) + warp_n * 64 + ni * 8 + tc;
            float* cc = acc[mi][ni];
            #pragma unroll
            for (int half = 0; half < 2; half++) {
                const int r = row + half * 8;
                float2 val = half ? make_float2(cc[2], cc[3]) : make_float2(cc[0], cc[1]);
                if (OMODE == 0) {
                    *(float2*)(outF + (size_t)r * ND + col) = val;
                } else {
                    val.x *= scale; val.y *= scale;
                    const int b = r >> 11, s = r & (NS - 1);
                    const int h = col >> 6, ch = col & 63;
                    __nv_bfloat162 hi = __floats2bfloat162_rn(val.x, val.y);
                    __nv_bfloat162 lo = __floats2bfloat162_rn(
                        val.x - __bfloat162float(hi.x), val.y - __bfloat162float(hi.y));
                    __nv_bfloat16* base = hdst
                        + (((size_t)(b * NH + h) * 2) * NS + s) * 64 + ch;
                    *(__nv_bfloat162*)base           = hi;
                    *(__nv_bfloat162*)(base + NS*64) = lo;
                }
            }
        }
    }
}

// ---------------------------------------------------------------------------
// HMMA causal flash attention. CTA = (bh, 128 q-rows). 4 warps x 32 rows.
// QK^T 3 passes; softmax fp32; PV 3 passes. kv tiles of 64, double-buffered.
// Epilogue writes split-bf16 [hi|lo|hi] rows of the Wo GEMM's A operand.
// ---------------------------------------------------------------------------
static constexpr int ATTN_SMEM = 32768 + 2 * 32768;  // 98304

__global__ void __launch_bounds__(128)
fattn(const __nv_bfloat16* __restrict__ Qg, const __nv_bfloat16* __restrict__ Kg,
      const __nv_bfloat16* __restrict__ Vg, __nv_bfloat16* __restrict__ As)
{
    extern __shared__ __align__(1024) char sm[];
    const uint32_t sb = smem_u32(sm);
    const int bh  = blockIdx.x;
    const int qt  = (int)gridDim.y - 1 - (int)blockIdx.y;  // big tiles first
    const int tid = threadIdx.x, lane = tid & 31, w = tid >> 5;

    const __nv_bfloat16* Qbh = Qg + (size_t)bh * 2 * NS * 64;
    const __nv_bfloat16* Kbh = Kg + (size_t)bh * 2 * NS * 64;
    const __nv_bfloat16* Vbh = Vg + (size_t)bh * 2 * NS * 64;

    #pragma unroll
    for (int i = 0; i < 16; i++) {
        int c = tid + i * 128;
        int p = c >> 10, r = (c >> 3) & 127, col16 = c & 7;
        uint4 v = *(const uint4*)(Qbh + (size_t)p * NS * 64
                                  + (size_t)(qt * 128 + r) * 64 + col16 * 8);
        uint32_t off = (uint32_t)(r * 128 + col16 * 16);
        *(uint4*)(sm + p * 16384 + (off ^ ((off >> 3) & 0x70))) = v;
    }

    const int nkt = 2 * qt + 2;

    auto load_kv = [&](int kt, int buf) {
        const int kv0 = kt * 64;
        #pragma unroll
        for (int i = 0; i < 16; i++) {
            int c = tid + i * 128;
            int p = c >> 9;
            int r = (c >> 3) & 63, col16 = c & 7;
            const __nv_bfloat16* src = (p < 2 ? Kbh : Vbh)
                + (size_t)(p & 1) * NS * 64 + (size_t)(kv0 + r) * 64 + col16 * 8;
            uint32_t off = (uint32_t)(r * 128 + col16 * 16);
            cpasync16(sb + 32768 + buf * 32768 + p * 8192 + (off ^ ((off >> 3) & 0x70)), src);
        }
        cp_commit();
    };

    load_kv(0, 0);

    float m[2][2], l[2][2];
    #pragma unroll
    for (int a = 0; a < 2; a++)
        #pragma unroll
        for (int b = 0; b < 2; b++) { m[a][b] = -1e30f; l[a][b] = 0.f; }

    float o[2][8][4];
    #pragma unroll
    for (int a = 0; a < 2; a++)
        #pragma unroll
        for (int b = 0; b < 8; b++)
            #pragma unroll
            for (int c = 0; c < 4; c++) o[a][b][c] = 0.f;

    const int qw0 = qt * 128 + w * 32;
    const uint32_t qoff[3] = {0u, 16384u, 0u};
    const uint32_t koff[3] = {0u, 0u, 8192u};

    for (int kt = 0; kt < nkt; kt++) {
        if (kt + 1 < nkt) {
            load_kv(kt + 1, (kt + 1) & 1);
            asm volatile("cp.async.wait_group 1;" ::: "memory");
        } else {
            asm volatile("cp.async.wait_group 0;" ::: "memory");
        }
        __syncthreads();

        if (kt * 64 <= qw0 + 31) {
            const uint32_t sK = sb + 32768 + (uint32_t)(kt & 1) * 32768u;
            const uint32_t sV = sK + 16384u;

            float s_[2][8][4];
            #pragma unroll
            for (int a = 0; a < 2; a++)
                #pragma unroll
                for (int b = 0; b < 8; b++)
                    #pragma unroll
                    for (int c = 0; c < 4; c++) s_[a][b][c] = 0.f;

            #pragma unroll
            for (int ps = 0; ps < 3; ps++) {
                #pragma unroll
                for (int ks = 0; ks < 4; ks++) {
                    uint32_t a[2][4];
                    #pragma unroll
                    for (int mi = 0; mi < 2; mi++) {
                        uint32_t off = (uint32_t)((w * 32 + mi * 16 + (lane & 15)) * 128
                                                  + (ks * 2 + (lane >> 4)) * 16);
                        ldsm4(a[mi], sb + qoff[ps] + (off ^ ((off >> 3) & 0x70)));
                    }
                    uint32_t bb[4][4];
                    #pragma unroll
                    for (int nj = 0; nj < 4; nj++) {
                        uint32_t off = (uint32_t)((nj * 16 + (lane & 15)) * 128
                                                  + (ks * 2 + (lane >> 4)) * 16);
                        ldsm4(bb[nj], sK + koff[ps] + (off ^ ((off >> 3) & 0x70)));
                    }
                    #pragma unroll
                    for (int mi = 0; mi < 2; mi++)
                        #pragma unroll
                        for (int ni = 0; ni < 8; ni++)
                            mma16816(s_[mi][ni], a[mi],
                                     bb[ni >> 1][ni & 1], bb[ni >> 1][2 + (ni & 1)]);
                }
            }

            if (kt * 64 + 63 > qw0) {
                #pragma unroll
                for (int mi = 0; mi < 2; mi++)
                    #pragma unroll
                    for (int ni = 0; ni < 8; ni++)
                        #pragma unroll
                        for (int c = 0; c < 4; c++) {
                            int qr = qw0 + mi * 16 + ((c >> 1) << 3) + (lane >> 2);
                            int kc = kt * 64 + ni * 8 + ((lane & 3) << 1) + (c & 1);
                            if (kc > qr) s_[mi][ni][c] = -1e30f;
                        }
            }

            #pragma unroll
            for (int mi = 0; mi < 2; mi++)
                #pragma unroll
                for (int rh = 0; rh < 2; rh++) {
                    float mx = -1e30f;
                    #pragma unroll
                    for (int ni = 0; ni < 8; ni++)
                        mx = fmaxf(mx, fmaxf(s_[mi][ni][rh*2], s_[mi][ni][rh*2+1]));
                    mx = fmaxf(mx, __shfl_xor_sync(0xffffffffu, mx, 1));
                    mx = fmaxf(mx, __shfl_xor_sync(0xffffffffu, mx, 2));
                    float mn = fmaxf(m[mi][rh], mx);
                    float sc = __expf(m[mi][rh] - mn);
                    m[mi][rh] = mn;
                    float sum = 0.f;
                    #pragma unroll
                    for (int ni = 0; ni < 8; ni++) {
                        float p0 = __expf(s_[mi][ni][rh*2]   - mn);
                        float p1 = __expf(s_[mi][ni][rh*2+1] - mn);
                        s_[mi][ni][rh*2] = p0; s_[mi][ni][rh*2+1] = p1;
                        sum += p0 + p1;
                    }
                    sum += __shfl_xor_sync(0xffffffffu, sum, 1);
                    sum += __shfl_xor_sync(0xffffffffu, sum, 2);
                    l[mi][rh] = l[mi][rh] * sc + sum;
                    #pragma unroll
                    for (int ni = 0; ni < 8; ni++) {
                        o[mi][ni][rh*2]   *= sc;
                        o[mi][ni][rh*2+1] *= sc;
                    }
                }

            #pragma unroll
            for (int ks = 0; ks < 4; ks++) {
                uint32_t ah[2][4], al[2][4];
                #pragma unroll
                for (int mi = 0; mi < 2; mi++) {
                    const float* t0 = s_[mi][2*ks];
                    const float* t1 = s_[mi][2*ks+1];
                    ah[mi][0] = packbf(t0[0], t0[1]);
                    ah[mi][1] = packbf(t0[2], t0[3]);
                    ah[mi][2] = packbf(t1[0], t1[1]);
                    ah[mi][3] = packbf(t1[2], t1[3]);
                    al[mi][0] = packlo(t0[0], t0[1], ah[mi][0]);
                    al[mi][1] = packlo(t0[2], t0[3], ah[mi][1]);
                    al[mi][2] = packlo(t1[0], t1[1], ah[mi][2]);
                    al[mi][3] = packlo(t1[2], t1[3], ah[mi][3]);
                }
                uint32_t bvh[4][4], bvl[4][4];
                #pragma unroll
                for (int nj = 0; nj < 4; nj++) {
                    uint32_t off = (uint32_t)((ks * 16 + (lane & 15)) * 128
                                              + (nj * 2 + (lane >> 4)) * 16);
                    off ^= (off >> 3) & 0x70;
                    ldsm4t(bvh[nj], sV + off);
                    ldsm4t(bvl[nj], sV + 8192 + off);
                }
                #pragma unroll
                for (int mi = 0; mi < 2; mi++)
                    #pragma unroll
                    for (int nd = 0; nd < 8; nd++) {
                        uint32_t b0 = bvh[nd >> 1][(nd & 1) * 2];
                        uint32_t b1 = bvh[nd >> 1][(nd & 1) * 2 + 1];
                        mma16816(o[mi][nd], ah[mi], b0, b1);
                        mma16816(o[mi][nd], al[mi], b0, b1);
                        uint32_t c0 = bvl[nd >> 1][(nd & 1) * 2];
                        uint32_t c1 = bvl[nd >> 1][(nd & 1) * 2 + 1];
                        mma16816(o[mi][nd], ah[mi], c0, c1);
                    }
            }
        }
        __syncthreads();
    }

    // epilogue: O/l -> split-bf16 rows [hi | lo | hi] of Wo GEMM's A operand
    const int b = bh >> 4, h = bh & 15;
    #pragma unroll
    for (int mi = 0; mi < 2; mi++)
        #pragma unroll
        for (int rh = 0; rh < 2; rh++) {
            float invl = 1.f / l[mi][rh];
            int row = qw0 + mi * 16 + rh * 8 + (lane >> 2);
            __nv_bfloat16* rbase = As + (size_t)(b * NS + row) * KX + h * 64;
            #pragma unroll
            for (int ni = 0; ni < 8; ni++) {
                float vx = o[mi][ni][rh*2] * invl;
                float vy = o[mi][ni][rh*2+1] * invl;
                __nv_bfloat162 hi = __floats2bfloat162_rn(vx, vy);
                __nv_bfloat162 lo = __floats2bfloat162_rn(
                    vx - __bfloat162float(hi.x), vy - __bfloat162float(hi.y));
                __nv_bfloat16* dst = rbase + ni * 8 + ((lane & 3) << 1);
                *(__nv_bfloat162*)dst          = hi;
                *(__nv_bfloat162*)(dst + 1024) = lo;
                *(__nv_bfloat162*)(dst + 2048) = hi;
            }
        }
}

// ---------------------------------------------------------------------------
extern "C" void kernel_launch(void* const* d_in, const int* in_sizes, int n_in,
                              void* d_out, int out_size)
{
    const float* x  = (const float*)d_in[0];
    const float* Wq = (const float*)d_in[1];
    const float* Wk = (const float*)d_in[2];
    const float* Wv = (const float*)d_in[3];
    const float* Wo = (const float*)d_in[4];
    float* out = (float*)d_out;

    __nv_bfloat16 *xs, *as, *wqkv, *wo, *q, *k, *v;
    cudaGetSymbolAddress((void**)&xs,   g_xs);
    cudaGetSymbolAddress((void**)&as,   g_as);
    cudaGetSymbolAddress((void**)&wqkv, g_wqkv);
    cudaGetSymbolAddress((void**)&wo,   g_wo);
    cudaGetSymbolAddress((void**)&q,    g_q);
    cudaGetSymbolAddress((void**)&k,    g_k);
    cudaGetSymbolAddress((void**)&v,    g_v);

    cudaFuncSetAttribute(gemm_mma<0>, cudaFuncAttributeMaxDynamicSharedMemorySize, GEMM_SMEM);
    cudaFuncSetAttribute(gemm_mma<1>, cudaFuncAttributeMaxDynamicSharedMemorySize, GEMM_SMEM);
    cudaFuncSetAttribute(fattn, cudaFuncAttributeMaxDynamicSharedMemorySize, ATTN_SMEM);

    split_act<<<MROWS * (ND/2) / 256, 256>>>(x, xs);
    split_w<<<dim3(ND * (ND/2) / 256, 4), 256>>>(Wq, Wk, Wv, Wo, wqkv, wo);

    // fused QKV projection: N = 3072
    gemm_mma<1><<<dim3(3 * ND / 128, MROWS / 128), 128, GEMM_SMEM>>>(
        xs, wqkv, nullptr, q, k, v);

    fattn<<<dim3(NB * NH, NS / 128), 128, ATTN_SMEM>>>(q, k, v, as);

    gemm_mma<0><<<dim3(ND / 128, MROWS / 128), 128, GEMM_SMEM>>>(
        as, wo, out, nullptr, nullptr, nullptr);
}